// round 1
// baseline (speedup 1.0000x reference)
#include <cuda_runtime.h>

#define HS 1024
#define NH 16
#define DH 64
#define B 4
#define SC 512
#define SE 2048

// -------------------- scratch (device globals; no allocation) --------------------
__device__ float g_Qc[(size_t)B * SC * HS];   // claim queries
__device__ float g_Kc[(size_t)B * SC * HS];   // claim keys
__device__ float g_Vc[(size_t)B * SC * HS];   // claim values
__device__ float g_Ac[(size_t)B * SC * HS];   // claim attention output
__device__ float g_Qe[(size_t)B * SE * HS];   // evidence queries
__device__ float g_Ke[(size_t)B * SE * HS];   // evidence keys
__device__ float g_Ve[(size_t)B * SE * HS];   // evidence values
__device__ float g_Ae[(size_t)B * SE * HS];   // evidence attention output

// -------------------- GEMM: C[M,1024] = A[M,1024] @ W^T + bias --------------------
// W is [1024 out, 1024 in] row-major (einsum 'bsh,oh->bso').
// 128x128x16 tile, 256 threads, 8x8 per-thread microtile.
__global__ __launch_bounds__(256) void gemm_bias(
    const float* __restrict__ A, const float* __restrict__ W,
    const float* __restrict__ bias, float* __restrict__ C, int M)
{
    const int K = HS;
    __shared__ float As[16][128];
    __shared__ float Bs[16][128];

    int tid = threadIdx.x;
    int bm = blockIdx.y * 128;
    int bn = blockIdx.x * 128;
    int ar = tid >> 2;        // 0..63
    int ac = tid & 3;         // 0..3 (float4 column within 16-wide k slab)
    int ty = tid >> 4;        // 0..15
    int tx = tid & 15;        // 0..15

    float acc[8][8];
#pragma unroll
    for (int i = 0; i < 8; i++)
#pragma unroll
        for (int j = 0; j < 8; j++) acc[i][j] = 0.f;

    for (int k0 = 0; k0 < K; k0 += 16) {
#pragma unroll
        for (int j = 0; j < 2; j++) {
            int row = ar + 64 * j;
            float4 va = *(const float4*)(A + (size_t)(bm + row) * K + k0 + ac * 4);
            As[ac * 4 + 0][row] = va.x;
            As[ac * 4 + 1][row] = va.y;
            As[ac * 4 + 2][row] = va.z;
            As[ac * 4 + 3][row] = va.w;
            float4 vb = *(const float4*)(W + (size_t)(bn + row) * K + k0 + ac * 4);
            Bs[ac * 4 + 0][row] = vb.x;
            Bs[ac * 4 + 1][row] = vb.y;
            Bs[ac * 4 + 2][row] = vb.z;
            Bs[ac * 4 + 3][row] = vb.w;
        }
        __syncthreads();
#pragma unroll
        for (int kk = 0; kk < 16; kk++) {
            float4 a0 = *(const float4*)&As[kk][ty * 8];
            float4 a1 = *(const float4*)&As[kk][ty * 8 + 4];
            float4 b0 = *(const float4*)&Bs[kk][tx * 8];
            float4 b1 = *(const float4*)&Bs[kk][tx * 8 + 4];
            float ra[8] = {a0.x, a0.y, a0.z, a0.w, a1.x, a1.y, a1.z, a1.w};
            float rb[8] = {b0.x, b0.y, b0.z, b0.w, b1.x, b1.y, b1.z, b1.w};
#pragma unroll
            for (int i = 0; i < 8; i++)
#pragma unroll
                for (int j = 0; j < 8; j++) acc[i][j] += ra[i] * rb[j];
        }
        __syncthreads();
    }

#pragma unroll
    for (int i = 0; i < 8; i++) {
        size_t row = (size_t)(bm + ty * 8 + i);
        float* cp = C + row * HS + bn + tx * 8;
        const float* bp = bias + bn + tx * 8;
        float4 o0 = make_float4(acc[i][0] + bp[0], acc[i][1] + bp[1],
                                acc[i][2] + bp[2], acc[i][3] + bp[3]);
        float4 o1 = make_float4(acc[i][4] + bp[4], acc[i][5] + bp[5],
                                acc[i][6] + bp[6], acc[i][7] + bp[7]);
        *(float4*)cp = o0;
        *(float4*)(cp + 4) = o1;
    }
}

// -------------------- attention: flash-style, 1 thread = 1 query row --------------
// Q:[B,Sq,1024], K,V:[B,Sk,1024] (head h occupies cols h*64..h*64+63)
// mask:[B,Sk] int (0 -> score = -1e9), out:[B,Sq,1024]
__global__ __launch_bounds__(128) void attn_kernel(
    const float* __restrict__ Q, const float* __restrict__ K,
    const float* __restrict__ V, const int* __restrict__ mask,
    float* __restrict__ O, int Sq, int Sk)
{
    __shared__ float Ks[64][64];
    __shared__ float Vs[64][64];
    __shared__ int   ms[64];

    int b = blockIdx.z;
    int h = blockIdx.y;
    int tid = threadIdx.x;
    int qi = blockIdx.x * 128 + tid;

    float q[64], o[64];
    const float4* qp = (const float4*)(Q + (size_t)(b * Sq + qi) * HS + h * DH);
#pragma unroll
    for (int d = 0; d < 16; d++) {
        float4 v = qp[d];
        q[4 * d + 0] = v.x; q[4 * d + 1] = v.y;
        q[4 * d + 2] = v.z; q[4 * d + 3] = v.w;
    }
#pragma unroll
    for (int d = 0; d < 64; d++) o[d] = 0.f;

    float m = -1e30f, l = 0.f;

    for (int k0 = 0; k0 < Sk; k0 += 64) {
        __syncthreads();
        // load 64x64 K and V tiles (fully coalesced float4)
#pragma unroll
        for (int j = 0; j < 8; j++) {
            int f = tid + 128 * j;            // 0..1023 float4 index
            int row = f >> 4;                 // 0..63
            int c = f & 15;                   // 0..15
            size_t gi = (size_t)(b * Sk + k0 + row) * (HS / 4) + h * (DH / 4) + c;
            ((float4*)Ks)[f] = ((const float4*)K)[gi];
            ((float4*)Vs)[f] = ((const float4*)V)[gi];
        }
        if (tid < 64) ms[tid] = mask[b * Sk + k0 + tid];
        __syncthreads();

        for (int kk = 0; kk < 64; kk++) {
            const float4* kr = (const float4*)&Ks[kk][0];
            float s0 = 0.f, s1 = 0.f, s2 = 0.f, s3 = 0.f;
#pragma unroll
            for (int d = 0; d < 16; d++) {
                float4 kv = kr[d];
                s0 += q[4 * d + 0] * kv.x;
                s1 += q[4 * d + 1] * kv.y;
                s2 += q[4 * d + 2] * kv.z;
                s3 += q[4 * d + 3] * kv.w;
            }
            float s = ((s0 + s1) + (s2 + s3)) * 0.125f;
            if (ms[kk] == 0) s = -1e9f;

            const float4* vr = (const float4*)&Vs[kk][0];
            if (s <= m) {
                float p = __expf(s - m);
                l += p;
#pragma unroll
                for (int d = 0; d < 16; d++) {
                    float4 vv = vr[d];
                    o[4 * d + 0] += p * vv.x;
                    o[4 * d + 1] += p * vv.y;
                    o[4 * d + 2] += p * vv.z;
                    o[4 * d + 3] += p * vv.w;
                }
            } else {
                float sc = __expf(m - s);
                m = s;
                l = l * sc + 1.f;
#pragma unroll
                for (int d = 0; d < 16; d++) {
                    float4 vv = vr[d];
                    o[4 * d + 0] = o[4 * d + 0] * sc + vv.x;
                    o[4 * d + 1] = o[4 * d + 1] * sc + vv.y;
                    o[4 * d + 2] = o[4 * d + 2] * sc + vv.z;
                    o[4 * d + 3] = o[4 * d + 3] * sc + vv.w;
                }
            }
        }
    }

    float inv = 1.f / l;
    float4* op = (float4*)(O + (size_t)(b * Sq + qi) * HS + h * DH);
#pragma unroll
    for (int d = 0; d < 16; d++)
        op[d] = make_float4(o[4 * d + 0] * inv, o[4 * d + 1] * inv,
                            o[4 * d + 2] * inv, o[4 * d + 3] * inv);
}

// -------------------- fused residual add + LayerNorm --------------------
__global__ __launch_bounds__(256) void add_ln_kernel(
    const float* __restrict__ x, const float* __restrict__ att,
    const float* __restrict__ g, const float* __restrict__ bb,
    float* __restrict__ out)
{
    int row = blockIdx.x;
    int tid = threadIdx.x;
    const float4* x4 = (const float4*)(x + (size_t)row * HS);
    const float4* a4 = (const float4*)(att + (size_t)row * HS);
    float4 xv = x4[tid];
    float4 av = a4[tid];
    float v0 = xv.x + av.x, v1 = xv.y + av.y, v2 = xv.z + av.z, v3 = xv.w + av.w;

    float s = v0 + v1 + v2 + v3;
    float sq = v0 * v0 + v1 * v1 + v2 * v2 + v3 * v3;
#pragma unroll
    for (int off = 16; off > 0; off >>= 1) {
        s  += __shfl_xor_sync(0xffffffffu, s, off);
        sq += __shfl_xor_sync(0xffffffffu, sq, off);
    }
    __shared__ float ss[8], ssq[8];
    int wid = tid >> 5, lane = tid & 31;
    if (lane == 0) { ss[wid] = s; ssq[wid] = sq; }
    __syncthreads();
    s = 0.f; sq = 0.f;
#pragma unroll
    for (int w = 0; w < 8; w++) { s += ss[w]; sq += ssq[w]; }

    float mu = s * (1.f / HS);
    float var = sq * (1.f / HS) - mu * mu;
    float r = rsqrtf(var + 1e-5f);

    float4 gv = ((const float4*)g)[tid];
    float4 bv = ((const float4*)bb)[tid];
    float4 ov = make_float4((v0 - mu) * r * gv.x + bv.x,
                            (v1 - mu) * r * gv.y + bv.y,
                            (v2 - mu) * r * gv.z + bv.z,
                            (v3 - mu) * r * gv.w + bv.w);
    ((float4*)(out + (size_t)row * HS))[tid] = ov;
}

// -------------------- launcher --------------------
extern "C" void kernel_launch(void* const* d_in, const int* in_sizes, int n_in,
                              void* d_out, int out_size)
{
    (void)in_sizes; (void)n_in; (void)out_size;
    const float* x_c   = (const float*)d_in[0];
    const float* x_e   = (const float*)d_in[1];
    const int*   msk_c = (const int*)d_in[2];
    const int*   msk_e = (const int*)d_in[3];
    const float* W_cq = (const float*)d_in[4];  const float* b_cq = (const float*)d_in[5];
    const float* W_ek = (const float*)d_in[6];  const float* b_ek = (const float*)d_in[7];
    const float* W_ev = (const float*)d_in[8];  const float* b_ev = (const float*)d_in[9];
    const float* W_eq = (const float*)d_in[10]; const float* b_eq = (const float*)d_in[11];
    const float* W_ck = (const float*)d_in[12]; const float* b_ck = (const float*)d_in[13];
    const float* W_cv = (const float*)d_in[14]; const float* b_cv = (const float*)d_in[15];
    const float* ln_g = (const float*)d_in[16]; const float* ln_b = (const float*)d_in[17];
    float* out = (float*)d_out;

    float *Qc, *Kc, *Vc, *Ac, *Qe, *Ke, *Ve, *Ae;
    cudaGetSymbolAddress((void**)&Qc, g_Qc);
    cudaGetSymbolAddress((void**)&Kc, g_Kc);
    cudaGetSymbolAddress((void**)&Vc, g_Vc);
    cudaGetSymbolAddress((void**)&Ac, g_Ac);
    cudaGetSymbolAddress((void**)&Qe, g_Qe);
    cudaGetSymbolAddress((void**)&Ke, g_Ke);
    cudaGetSymbolAddress((void**)&Ve, g_Ve);
    cudaGetSymbolAddress((void**)&Ae, g_Ae);

    const int Mc = B * SC;   // 2048
    const int Me = B * SE;   // 8192

    dim3 gc(HS / 128, Mc / 128);
    dim3 ge(HS / 128, Me / 128);
    // projections
    gemm_bias<<<gc, 256>>>(x_c, W_cq, b_cq, Qc, Mc);
    gemm_bias<<<gc, 256>>>(x_c, W_ck, b_ck, Kc, Mc);
    gemm_bias<<<gc, 256>>>(x_c, W_cv, b_cv, Vc, Mc);
    gemm_bias<<<ge, 256>>>(x_e, W_ek, b_ek, Ke, Me);
    gemm_bias<<<ge, 256>>>(x_e, W_ev, b_ev, Ve, Me);
    gemm_bias<<<ge, 256>>>(x_e, W_eq, b_eq, Qe, Me);

    // cross attention: claim queries over evidence K/V (evidence_mask),
    //                  evidence queries over claim K/V (claim_mask)
    attn_kernel<<<dim3(SC / 128, NH, B), 128>>>(Qc, Ke, Ve, msk_e, Ac, SC, SE);
    attn_kernel<<<dim3(SE / 128, NH, B), 128>>>(Qe, Kc, Vc, msk_c, Ae, SE, SC);

    // residual + layernorm -> packed output (claim first, then evidence)
    add_ln_kernel<<<Mc, 256>>>(x_c, Ac, ln_g, ln_b, out);
    add_ln_kernel<<<Me, 256>>>(x_e, Ae, ln_g, ln_b, out + (size_t)Mc * HS);
}

// round 3
// speedup vs baseline: 1.4924x; 1.4924x over previous
#include <cuda_runtime.h>
#include <cuda_bf16.h>
#include <cstdint>

#define HS 1024
#define NH 16
#define DH 64
#define B 4
#define SC 512
#define SE 2048

// -------------------- scratch (device globals; no allocation) --------------------
__device__ float g_Qc[(size_t)B * SC * HS];
__device__ float g_Kc[(size_t)B * SC * HS];
__device__ float g_Vc[(size_t)B * SC * HS];
__device__ float g_Ac[(size_t)B * SC * HS];
__device__ float g_Qe[(size_t)B * SE * HS];
__device__ float g_Ke[(size_t)B * SE * HS];
__device__ float g_Ve[(size_t)B * SE * HS];
__device__ float g_Ae[(size_t)B * SE * HS];

// ==================== HMMA helpers ====================
__device__ __forceinline__ void mma_bf16(float* d, const uint32_t* a, const uint32_t* b) {
    asm volatile(
        "mma.sync.aligned.m16n8k16.row.col.f32.bf16.bf16.f32 "
        "{%0,%1,%2,%3}, {%4,%5,%6,%7}, {%8,%9}, {%0,%1,%2,%3};"
        : "+f"(d[0]), "+f"(d[1]), "+f"(d[2]), "+f"(d[3])
        : "r"(a[0]), "r"(a[1]), "r"(a[2]), "r"(a[3]), "r"(b[0]), "r"(b[1]));
}

__device__ __forceinline__ uint32_t pack_bf16(__nv_bfloat16 a, __nv_bfloat16 b) {
    __nv_bfloat162 p(a, b);
    return *(uint32_t*)&p;
}

__device__ __forceinline__ void cvt_split(float4 v, uint2& hi, uint2& lo) {
    __nv_bfloat16 h0 = __float2bfloat16(v.x);
    __nv_bfloat16 h1 = __float2bfloat16(v.y);
    __nv_bfloat16 h2 = __float2bfloat16(v.z);
    __nv_bfloat16 h3 = __float2bfloat16(v.w);
    __nv_bfloat16 l0 = __float2bfloat16(v.x - __bfloat162float(h0));
    __nv_bfloat16 l1 = __float2bfloat16(v.y - __bfloat162float(h1));
    __nv_bfloat16 l2 = __float2bfloat16(v.z - __bfloat162float(h2));
    __nv_bfloat16 l3 = __float2bfloat16(v.w - __bfloat162float(h3));
    hi = make_uint2(pack_bf16(h0, h1), pack_bf16(h2, h3));
    lo = make_uint2(pack_bf16(l0, l1), pack_bf16(l2, l3));
}

// ==================== GEMM: C[M,1024] = A[M,1024] @ W^T + bias ====================
// split-bf16 mma.sync, 128x128 CTA tile, warp tile 32x64, k-chunk 32, double buffer.
// smem row stride 80B (64B data + 16B pad) -> conflict-free fragment LDS.
#define ROWSTRIDE 80
#define SUBTILE   (128 * ROWSTRIDE)   // 10240 B
#define AH_OFF    0
#define AL_OFF    (1 * SUBTILE)
#define BH_OFF    (2 * SUBTILE)
#define BL_OFF    (3 * SUBTILE)
#define BUF_BYTES (4 * SUBTILE)       // 40960
#define GSMEM     (2 * BUF_BYTES)     // 81920

__global__ __launch_bounds__(256, 1) void gemm_hmma(
    const float* __restrict__ A, const float* __restrict__ W,
    const float* __restrict__ bias, float* __restrict__ C)
{
    extern __shared__ char smem[];
    const int tid = threadIdx.x;
    const int wid = tid >> 5;
    const int lane = tid & 31;
    const int g = lane >> 2;       // 0..7
    const int t = lane & 3;        // 0..3
    const int warpM = wid & 3;     // 0..3 -> rows 32 each
    const int warpN = wid >> 2;    // 0..1 -> cols 64 each
    const int bm = blockIdx.y * 128;
    const int bn = blockIdx.x * 128;

    float acc[2][8][4];
#pragma unroll
    for (int i = 0; i < 2; i++)
#pragma unroll
        for (int j = 0; j < 8; j++)
#pragma unroll
            for (int k = 0; k < 4; k++) acc[i][j][k] = 0.f;

    const int NC = HS / 32;        // 32 chunks

    float4 ra[4], rb[4];
    // prologue: load + store chunk 0
#pragma unroll
    for (int q = 0; q < 4; q++) {
        int f = tid + 256 * q;
        int row = f >> 3, kc = f & 7;
        ra[q] = *(const float4*)(A + (size_t)(bm + row) * HS + kc * 4);
        rb[q] = *(const float4*)(W + (size_t)(bn + row) * HS + kc * 4);
    }
#pragma unroll
    for (int q = 0; q < 4; q++) {
        int f = tid + 256 * q;
        int row = f >> 3, kc = f & 7;
        int off = row * ROWSTRIDE + kc * 8;
        uint2 hi, lo;
        cvt_split(ra[q], hi, lo);
        *(uint2*)(smem + AH_OFF + off) = hi;
        *(uint2*)(smem + AL_OFF + off) = lo;
        cvt_split(rb[q], hi, lo);
        *(uint2*)(smem + BH_OFF + off) = hi;
        *(uint2*)(smem + BL_OFF + off) = lo;
    }
    __syncthreads();

    for (int c = 0; c < NC; c++) {
        // prefetch next chunk into registers
        if (c + 1 < NC) {
            int k0 = (c + 1) * 32;
#pragma unroll
            for (int q = 0; q < 4; q++) {
                int f = tid + 256 * q;
                int row = f >> 3, kc = f & 7;
                ra[q] = *(const float4*)(A + (size_t)(bm + row) * HS + k0 + kc * 4);
                rb[q] = *(const float4*)(W + (size_t)(bn + row) * HS + k0 + kc * 4);
            }
        }

        char* buf = smem + (c & 1) * BUF_BYTES;
#pragma unroll
        for (int s = 0; s < 2; s++) {
            const int kb = s * 32 + 4 * t;
            uint32_t ah[2][4], al[2][4];
#pragma unroll
            for (int i = 0; i < 2; i++) {
                int r = warpM * 32 + 16 * i + g;
                const char* pa = buf + AH_OFF + r * ROWSTRIDE + kb;
                ah[i][0] = *(const uint32_t*)(pa);
                ah[i][1] = *(const uint32_t*)(pa + 8 * ROWSTRIDE);
                ah[i][2] = *(const uint32_t*)(pa + 16);
                ah[i][3] = *(const uint32_t*)(pa + 8 * ROWSTRIDE + 16);
                const char* pl = buf + AL_OFF + r * ROWSTRIDE + kb;
                al[i][0] = *(const uint32_t*)(pl);
                al[i][1] = *(const uint32_t*)(pl + 8 * ROWSTRIDE);
                al[i][2] = *(const uint32_t*)(pl + 16);
                al[i][3] = *(const uint32_t*)(pl + 8 * ROWSTRIDE + 16);
            }
#pragma unroll
            for (int j = 0; j < 8; j++) {
                int nr = warpN * 64 + 8 * j + g;
                const char* pbh = buf + BH_OFF + nr * ROWSTRIDE + kb;
                const char* pbl = buf + BL_OFF + nr * ROWSTRIDE + kb;
                uint32_t bh[2], bl[2];
                bh[0] = *(const uint32_t*)(pbh);
                bh[1] = *(const uint32_t*)(pbh + 16);
                bl[0] = *(const uint32_t*)(pbl);
                bl[1] = *(const uint32_t*)(pbl + 16);
#pragma unroll
                for (int i = 0; i < 2; i++) {
                    mma_bf16(acc[i][j], ah[i], bh);
                    mma_bf16(acc[i][j], ah[i], bl);
                    mma_bf16(acc[i][j], al[i], bh);
                }
            }
        }

        if (c + 1 < NC) {
            char* nbuf = smem + ((c + 1) & 1) * BUF_BYTES;
#pragma unroll
            for (int q = 0; q < 4; q++) {
                int f = tid + 256 * q;
                int row = f >> 3, kc = f & 7;
                int off = row * ROWSTRIDE + kc * 8;
                uint2 hi, lo;
                cvt_split(ra[q], hi, lo);
                *(uint2*)(nbuf + AH_OFF + off) = hi;
                *(uint2*)(nbuf + AL_OFF + off) = lo;
                cvt_split(rb[q], hi, lo);
                *(uint2*)(nbuf + BH_OFF + off) = hi;
                *(uint2*)(nbuf + BL_OFF + off) = lo;
            }
        }
        __syncthreads();
    }

    // epilogue: d0,d1 -> (row, col..col+1); d2,d3 -> (row+8, ...)
#pragma unroll
    for (int i = 0; i < 2; i++) {
        int row0 = bm + warpM * 32 + 16 * i + g;
#pragma unroll
        for (int j = 0; j < 8; j++) {
            int col = bn + warpN * 64 + 8 * j + 2 * t;
            float2 bv = *(const float2*)(bias + col);
            *(float2*)(C + (size_t)row0 * HS + col) =
                make_float2(acc[i][j][0] + bv.x, acc[i][j][1] + bv.y);
            *(float2*)(C + (size_t)(row0 + 8) * HS + col) =
                make_float2(acc[i][j][2] + bv.x, acc[i][j][3] + bv.y);
        }
    }
}

// -------------------- attention: flash-style, 1 thread = 1 query row --------------
__global__ __launch_bounds__(128) void attn_kernel(
    const float* __restrict__ Q, const float* __restrict__ K,
    const float* __restrict__ V, const int* __restrict__ mask,
    float* __restrict__ O, int Sq, int Sk)
{
    __shared__ float Ks[64][64];
    __shared__ float Vs[64][64];
    __shared__ float ms[64];

    int b = blockIdx.z;
    int h = blockIdx.y;
    int tid = threadIdx.x;
    int qi = blockIdx.x * 128 + tid;

    float q[64], o[64];
    const float4* qp = (const float4*)(Q + (size_t)(b * Sq + qi) * HS + h * DH);
#pragma unroll
    for (int d = 0; d < 16; d++) {
        float4 v = qp[d];
        q[4 * d + 0] = v.x; q[4 * d + 1] = v.y;
        q[4 * d + 2] = v.z; q[4 * d + 3] = v.w;
    }
#pragma unroll
    for (int d = 0; d < 64; d++) o[d] = 0.f;

    float m = -1e30f, l = 0.f;

    for (int k0 = 0; k0 < Sk; k0 += 64) {
        __syncthreads();
#pragma unroll
        for (int j = 0; j < 8; j++) {
            int f = tid + 128 * j;
            int row = f >> 4;
            int c = f & 15;
            size_t gi = (size_t)(b * Sk + k0 + row) * (HS / 4) + h * (DH / 4) + c;
            ((float4*)Ks)[f] = ((const float4*)K)[gi];
            ((float4*)Vs)[f] = ((const float4*)V)[gi];
        }
        if (tid < 64) ms[tid] = (mask[b * Sk + k0 + tid] == 0) ? -1e9f : 0.f;
        __syncthreads();

        for (int kk = 0; kk < 64; kk++) {
            const float4* kr = (const float4*)&Ks[kk][0];
            float s0 = 0.f, s1 = 0.f, s2 = 0.f, s3 = 0.f;
#pragma unroll
            for (int d = 0; d < 16; d++) {
                float4 kv = kr[d];
                s0 += q[4 * d + 0] * kv.x;
                s1 += q[4 * d + 1] * kv.y;
                s2 += q[4 * d + 2] * kv.z;
                s3 += q[4 * d + 3] * kv.w;
            }
            float s = fmaf((s0 + s1) + (s2 + s3), 0.125f, ms[kk]);

            const float4* vr = (const float4*)&Vs[kk][0];
            if (s <= m) {
                float p = __expf(s - m);
                l += p;
#pragma unroll
                for (int d = 0; d < 16; d++) {
                    float4 vv = vr[d];
                    o[4 * d + 0] += p * vv.x;
                    o[4 * d + 1] += p * vv.y;
                    o[4 * d + 2] += p * vv.z;
                    o[4 * d + 3] += p * vv.w;
                }
            } else {
                float sc = __expf(m - s);
                m = s;
                l = l * sc + 1.f;
#pragma unroll
                for (int d = 0; d < 16; d++) {
                    float4 vv = vr[d];
                    o[4 * d + 0] = o[4 * d + 0] * sc + vv.x;
                    o[4 * d + 1] = o[4 * d + 1] * sc + vv.y;
                    o[4 * d + 2] = o[4 * d + 2] * sc + vv.z;
                    o[4 * d + 3] = o[4 * d + 3] * sc + vv.w;
                }
            }
        }
    }

    float inv = 1.f / l;
    float4* op = (float4*)(O + (size_t)(b * Sq + qi) * HS + h * DH);
#pragma unroll
    for (int d = 0; d < 16; d++)
        op[d] = make_float4(o[4 * d + 0] * inv, o[4 * d + 1] * inv,
                            o[4 * d + 2] * inv, o[4 * d + 3] * inv);
}

// -------------------- fused residual add + LayerNorm --------------------
__global__ __launch_bounds__(256) void add_ln_kernel(
    const float* __restrict__ x, const float* __restrict__ att,
    const float* __restrict__ g, const float* __restrict__ bb,
    float* __restrict__ out)
{
    int row = blockIdx.x;
    int tid = threadIdx.x;
    const float4* x4 = (const float4*)(x + (size_t)row * HS);
    const float4* a4 = (const float4*)(att + (size_t)row * HS);
    float4 xv = x4[tid];
    float4 av = a4[tid];
    float v0 = xv.x + av.x, v1 = xv.y + av.y, v2 = xv.z + av.z, v3 = xv.w + av.w;

    float s = v0 + v1 + v2 + v3;
    float sq = v0 * v0 + v1 * v1 + v2 * v2 + v3 * v3;
#pragma unroll
    for (int off = 16; off > 0; off >>= 1) {
        s  += __shfl_xor_sync(0xffffffffu, s, off);
        sq += __shfl_xor_sync(0xffffffffu, sq, off);
    }
    __shared__ float ss[8], ssq[8];
    int wid = tid >> 5, lane = tid & 31;
    if (lane == 0) { ss[wid] = s; ssq[wid] = sq; }
    __syncthreads();
    s = 0.f; sq = 0.f;
#pragma unroll
    for (int w = 0; w < 8; w++) { s += ss[w]; sq += ssq[w]; }

    float mu = s * (1.f / HS);
    float var = sq * (1.f / HS) - mu * mu;
    float r = rsqrtf(var + 1e-5f);

    float4 gv = ((const float4*)g)[tid];
    float4 bv = ((const float4*)bb)[tid];
    float4 ov = make_float4((v0 - mu) * r * gv.x + bv.x,
                            (v1 - mu) * r * gv.y + bv.y,
                            (v2 - mu) * r * gv.z + bv.z,
                            (v3 - mu) * r * gv.w + bv.w);
    ((float4*)(out + (size_t)row * HS))[tid] = ov;
}

// -------------------- launcher --------------------
extern "C" void kernel_launch(void* const* d_in, const int* in_sizes, int n_in,
                              void* d_out, int out_size)
{
    (void)in_sizes; (void)n_in; (void)out_size;
    const float* x_c   = (const float*)d_in[0];
    const float* x_e   = (const float*)d_in[1];
    const int*   msk_c = (const int*)d_in[2];
    const int*   msk_e = (const int*)d_in[3];
    const float* W_cq = (const float*)d_in[4];  const float* b_cq = (const float*)d_in[5];
    const float* W_ek = (const float*)d_in[6];  const float* b_ek = (const float*)d_in[7];
    const float* W_ev = (const float*)d_in[8];  const float* b_ev = (const float*)d_in[9];
    const float* W_eq = (const float*)d_in[10]; const float* b_eq = (const float*)d_in[11];
    const float* W_ck = (const float*)d_in[12]; const float* b_ck = (const float*)d_in[13];
    const float* W_cv = (const float*)d_in[14]; const float* b_cv = (const float*)d_in[15];
    const float* ln_g = (const float*)d_in[16]; const float* ln_b = (const float*)d_in[17];
    float* out = (float*)d_out;

    float *Qc, *Kc, *Vc, *Ac, *Qe, *Ke, *Ve, *Ae;
    cudaGetSymbolAddress((void**)&Qc, g_Qc);
    cudaGetSymbolAddress((void**)&Kc, g_Kc);
    cudaGetSymbolAddress((void**)&Vc, g_Vc);
    cudaGetSymbolAddress((void**)&Ac, g_Ac);
    cudaGetSymbolAddress((void**)&Qe, g_Qe);
    cudaGetSymbolAddress((void**)&Ke, g_Ke);
    cudaGetSymbolAddress((void**)&Ve, g_Ve);
    cudaGetSymbolAddress((void**)&Ae, g_Ae);

    cudaFuncSetAttribute(gemm_hmma, cudaFuncAttributeMaxDynamicSharedMemorySize, GSMEM);

    const int Mc = B * SC;   // 2048
    const int Me = B * SE;   // 8192

    dim3 gc(HS / 128, Mc / 128);   // (8, 16)
    dim3 ge(HS / 128, Me / 128);   // (8, 64)
    gemm_hmma<<<gc, 256, GSMEM>>>(x_c, W_cq, b_cq, Qc);
    gemm_hmma<<<gc, 256, GSMEM>>>(x_c, W_ck, b_ck, Kc);
    gemm_hmma<<<gc, 256, GSMEM>>>(x_c, W_cv, b_cv, Vc);
    gemm_hmma<<<ge, 256, GSMEM>>>(x_e, W_ek, b_ek, Ke);
    gemm_hmma<<<ge, 256, GSMEM>>>(x_e, W_ev, b_ev, Ve);
    gemm_hmma<<<ge, 256, GSMEM>>>(x_e, W_eq, b_eq, Qe);

    attn_kernel<<<dim3(SC / 128, NH, B), 128>>>(Qc, Ke, Ve, msk_e, Ac, SC, SE);
    attn_kernel<<<dim3(SE / 128, NH, B), 128>>>(Qe, Kc, Vc, msk_c, Ae, SE, SC);

    add_ln_kernel<<<Mc, 256>>>(x_c, Ac, ln_g, ln_b, out);
    add_ln_kernel<<<Me, 256>>>(x_e, Ae, ln_g, ln_b, out + (size_t)Mc * HS);
}

// round 4
// speedup vs baseline: 2.8900x; 1.9365x over previous
#include <cuda_runtime.h>
#include <cuda_bf16.h>
#include <cstdint>

#define HS 1024
#define NH 16
#define DH 64
#define B 4
#define SC 512
#define SE 2048

// -------------------- scratch (device globals; no allocation) --------------------
__device__ float g_Qc[(size_t)B * SC * HS];
__device__ float g_Kc[(size_t)B * SC * HS];
__device__ float g_Vc[(size_t)B * SC * HS];
__device__ float g_Ac[(size_t)B * SC * HS];
__device__ float g_Qe[(size_t)B * SE * HS];
__device__ float g_Ke[(size_t)B * SE * HS];
__device__ float g_Ve[(size_t)B * SE * HS];
__device__ float g_Ae[(size_t)B * SE * HS];
// bf16 split K / V-transposed per head
__device__ __align__(256) __nv_bfloat16 g_Keh[(size_t)B * NH * SE * DH];
__device__ __align__(256) __nv_bfloat16 g_Kel[(size_t)B * NH * SE * DH];
__device__ __align__(256) __nv_bfloat16 g_Veth[(size_t)B * NH * SE * DH];
__device__ __align__(256) __nv_bfloat16 g_Vetl[(size_t)B * NH * SE * DH];
__device__ __align__(256) __nv_bfloat16 g_Kch[(size_t)B * NH * SC * DH];
__device__ __align__(256) __nv_bfloat16 g_Kcl[(size_t)B * NH * SC * DH];
__device__ __align__(256) __nv_bfloat16 g_Vcth[(size_t)B * NH * SC * DH];
__device__ __align__(256) __nv_bfloat16 g_Vctl[(size_t)B * NH * SC * DH];

// ==================== helpers ====================
__device__ __forceinline__ void mma_bf16(float* d, const uint32_t* a, const uint32_t* b) {
    asm volatile(
        "mma.sync.aligned.m16n8k16.row.col.f32.bf16.bf16.f32 "
        "{%0,%1,%2,%3}, {%4,%5,%6,%7}, {%8,%9}, {%0,%1,%2,%3};"
        : "+f"(d[0]), "+f"(d[1]), "+f"(d[2]), "+f"(d[3])
        : "r"(a[0]), "r"(a[1]), "r"(a[2]), "r"(a[3]), "r"(b[0]), "r"(b[1]));
}

__device__ __forceinline__ uint32_t pack_bf16(__nv_bfloat16 a, __nv_bfloat16 b) {
    __nv_bfloat162 p(a, b);
    return *(uint32_t*)&p;
}

__device__ __forceinline__ uint32_t cvt2(float hi, float lo) {
    uint32_t r;
    asm("cvt.rn.satfinite.bf16x2.f32 %0, %1, %2;" : "=r"(r) : "f"(hi), "f"(lo));
    return r;
}

__device__ __forceinline__ void cvt_split(float4 v, uint2& hi, uint2& lo) {
    __nv_bfloat16 h0 = __float2bfloat16(v.x);
    __nv_bfloat16 h1 = __float2bfloat16(v.y);
    __nv_bfloat16 h2 = __float2bfloat16(v.z);
    __nv_bfloat16 h3 = __float2bfloat16(v.w);
    __nv_bfloat16 l0 = __float2bfloat16(v.x - __bfloat162float(h0));
    __nv_bfloat16 l1 = __float2bfloat16(v.y - __bfloat162float(h1));
    __nv_bfloat16 l2 = __float2bfloat16(v.z - __bfloat162float(h2));
    __nv_bfloat16 l3 = __float2bfloat16(v.w - __bfloat162float(h3));
    hi = make_uint2(pack_bf16(h0, h1), pack_bf16(h2, h3));
    lo = make_uint2(pack_bf16(l0, l1), pack_bf16(l2, l3));
}

__device__ __forceinline__ uint32_t smem_u32(const void* p) {
    uint32_t a;
    asm("{ .reg .u64 t; cvta.to.shared.u64 t, %1; cvt.u32.u64 %0, t; }" : "=r"(a) : "l"(p));
    return a;
}

__device__ __forceinline__ void cp16(uint32_t dst, const void* src) {
    asm volatile("cp.async.cg.shared.global [%0], [%1], 16;" :: "r"(dst), "l"(src));
}

// exp2 on the FMA pipe: deg-5 Taylor on [-0.5, 0.5], max rel err ~2.4e-6
__device__ __forceinline__ float exp2p(float d) {
    d = fmaxf(d, -126.f);
    int i = __float2int_rn(d);
    float fr = d - (float)i;
    float p = 1.3333558146e-3f;
    p = fmaf(p, fr, 9.6181291076e-3f);
    p = fmaf(p, fr, 5.5504108664e-2f);
    p = fmaf(p, fr, 2.4022650696e-1f);
    p = fmaf(p, fr, 6.9314718056e-1f);
    p = fmaf(p, fr, 1.0f);
    return p * __int_as_float((i + 127) << 23);
}

#define CSC 0.1803368801111694f   // log2(e)/8
#define MASKADD (-24000.0f)

// ==================== GEMM (unchanged from round 3) ====================
#define ROWSTRIDE 80
#define SUBTILE   (128 * ROWSTRIDE)
#define AH_OFF    0
#define AL_OFF    (1 * SUBTILE)
#define BH_OFF    (2 * SUBTILE)
#define BL_OFF    (3 * SUBTILE)
#define BUF_BYTES (4 * SUBTILE)
#define GSMEM     (2 * BUF_BYTES)

__global__ __launch_bounds__(256, 1) void gemm_hmma(
    const float* __restrict__ A, const float* __restrict__ W,
    const float* __restrict__ bias, float* __restrict__ C)
{
    extern __shared__ char smem[];
    const int tid = threadIdx.x;
    const int wid = tid >> 5;
    const int lane = tid & 31;
    const int g = lane >> 2;
    const int t = lane & 3;
    const int warpM = wid & 3;
    const int warpN = wid >> 2;
    const int bm = blockIdx.y * 128;
    const int bn = blockIdx.x * 128;

    float acc[2][8][4];
#pragma unroll
    for (int i = 0; i < 2; i++)
#pragma unroll
        for (int j = 0; j < 8; j++)
#pragma unroll
            for (int k = 0; k < 4; k++) acc[i][j][k] = 0.f;

    const int NC = HS / 32;

    float4 ra[4], rb[4];
#pragma unroll
    for (int q = 0; q < 4; q++) {
        int f = tid + 256 * q;
        int row = f >> 3, kc = f & 7;
        ra[q] = *(const float4*)(A + (size_t)(bm + row) * HS + kc * 4);
        rb[q] = *(const float4*)(W + (size_t)(bn + row) * HS + kc * 4);
    }
#pragma unroll
    for (int q = 0; q < 4; q++) {
        int f = tid + 256 * q;
        int row = f >> 3, kc = f & 7;
        int off = row * ROWSTRIDE + kc * 8;
        uint2 hi, lo;
        cvt_split(ra[q], hi, lo);
        *(uint2*)(smem + AH_OFF + off) = hi;
        *(uint2*)(smem + AL_OFF + off) = lo;
        cvt_split(rb[q], hi, lo);
        *(uint2*)(smem + BH_OFF + off) = hi;
        *(uint2*)(smem + BL_OFF + off) = lo;
    }
    __syncthreads();

    for (int c = 0; c < NC; c++) {
        if (c + 1 < NC) {
            int k0 = (c + 1) * 32;
#pragma unroll
            for (int q = 0; q < 4; q++) {
                int f = tid + 256 * q;
                int row = f >> 3, kc = f & 7;
                ra[q] = *(const float4*)(A + (size_t)(bm + row) * HS + k0 + kc * 4);
                rb[q] = *(const float4*)(W + (size_t)(bn + row) * HS + k0 + kc * 4);
            }
        }

        char* buf = smem + (c & 1) * BUF_BYTES;
#pragma unroll
        for (int s = 0; s < 2; s++) {
            const int kb = s * 32 + 4 * t;
            uint32_t ah[2][4], al[2][4];
#pragma unroll
            for (int i = 0; i < 2; i++) {
                int r = warpM * 32 + 16 * i + g;
                const char* pa = buf + AH_OFF + r * ROWSTRIDE + kb;
                ah[i][0] = *(const uint32_t*)(pa);
                ah[i][1] = *(const uint32_t*)(pa + 8 * ROWSTRIDE);
                ah[i][2] = *(const uint32_t*)(pa + 16);
                ah[i][3] = *(const uint32_t*)(pa + 8 * ROWSTRIDE + 16);
                const char* pl = buf + AL_OFF + r * ROWSTRIDE + kb;
                al[i][0] = *(const uint32_t*)(pl);
                al[i][1] = *(const uint32_t*)(pl + 8 * ROWSTRIDE);
                al[i][2] = *(const uint32_t*)(pl + 16);
                al[i][3] = *(const uint32_t*)(pl + 8 * ROWSTRIDE + 16);
            }
#pragma unroll
            for (int j = 0; j < 8; j++) {
                int nr = warpN * 64 + 8 * j + g;
                const char* pbh = buf + BH_OFF + nr * ROWSTRIDE + kb;
                const char* pbl = buf + BL_OFF + nr * ROWSTRIDE + kb;
                uint32_t bh[2], bl[2];
                bh[0] = *(const uint32_t*)(pbh);
                bh[1] = *(const uint32_t*)(pbh + 16);
                bl[0] = *(const uint32_t*)(pbl);
                bl[1] = *(const uint32_t*)(pbl + 16);
#pragma unroll
                for (int i = 0; i < 2; i++) {
                    mma_bf16(acc[i][j], ah[i], bh);
                    mma_bf16(acc[i][j], ah[i], bl);
                    mma_bf16(acc[i][j], al[i], bh);
                }
            }
        }

        if (c + 1 < NC) {
            char* nbuf = smem + ((c + 1) & 1) * BUF_BYTES;
#pragma unroll
            for (int q = 0; q < 4; q++) {
                int f = tid + 256 * q;
                int row = f >> 3, kc = f & 7;
                int off = row * ROWSTRIDE + kc * 8;
                uint2 hi, lo;
                cvt_split(ra[q], hi, lo);
                *(uint2*)(nbuf + AH_OFF + off) = hi;
                *(uint2*)(nbuf + AL_OFF + off) = lo;
                cvt_split(rb[q], hi, lo);
                *(uint2*)(nbuf + BH_OFF + off) = hi;
                *(uint2*)(nbuf + BL_OFF + off) = lo;
            }
        }
        __syncthreads();
    }

#pragma unroll
    for (int i = 0; i < 2; i++) {
        int row0 = bm + warpM * 32 + 16 * i + g;
#pragma unroll
        for (int j = 0; j < 8; j++) {
            int col = bn + warpN * 64 + 8 * j + 2 * t;
            float2 bv = *(const float2*)(bias + col);
            *(float2*)(C + (size_t)row0 * HS + col) =
                make_float2(acc[i][j][0] + bv.x, acc[i][j][1] + bv.y);
            *(float2*)(C + (size_t)(row0 + 8) * HS + col) =
                make_float2(acc[i][j][2] + bv.x, acc[i][j][3] + bv.y);
        }
    }
}

// ==================== K/V prep: fp32 -> split bf16 (K row-major, V transposed) ====
__global__ __launch_bounds__(256) void prep_kv(
    const float* __restrict__ K, const float* __restrict__ V,
    __nv_bfloat16* __restrict__ Kh, __nv_bfloat16* __restrict__ Kl,
    __nv_bfloat16* __restrict__ Vth, __nv_bfloat16* __restrict__ Vtl, int Sk)
{
    __shared__ float vs[64][65];
    const int tid = threadIdx.x;
    const int b = blockIdx.z, h = blockIdx.y;
    const int s0 = blockIdx.x * 64;
    const int bh = b * NH + h;

    // K: straight copy-convert
#pragma unroll
    for (int i = 0; i < 4; i++) {
        int f = tid + 256 * i;
        int r = f >> 4, c4 = f & 15;
        float4 v = *(const float4*)(K + (size_t)(b * Sk + s0 + r) * HS + h * DH + c4 * 4);
        uint2 hi, lo;
        cvt_split(v, hi, lo);
        size_t o = ((size_t)(bh * Sk + s0 + r)) * DH + c4 * 4;
        *(uint2*)(Kh + o) = hi;
        *(uint2*)(Kl + o) = lo;
    }
    // V: stage rows then write transposed
#pragma unroll
    for (int i = 0; i < 4; i++) {
        int f = tid + 256 * i;
        int r = f >> 4, c4 = f & 15;
        float4 v = *(const float4*)(V + (size_t)(b * Sk + s0 + r) * HS + h * DH + c4 * 4);
        vs[r][c4 * 4 + 0] = v.x;
        vs[r][c4 * 4 + 1] = v.y;
        vs[r][c4 * 4 + 2] = v.z;
        vs[r][c4 * 4 + 3] = v.w;
    }
    __syncthreads();
#pragma unroll
    for (int i = 0; i < 8; i++) {
        int f = tid + 256 * i;
        int d = f >> 5, sp = f & 31;
        float v0 = vs[2 * sp][d], v1 = vs[2 * sp + 1][d];
        uint32_t hi = cvt2(v1, v0);
        float f0 = __int_as_float(hi << 16);
        float f1 = __int_as_float(hi & 0xffff0000u);
        uint32_t lo = cvt2(v1 - f1, v0 - f0);
        size_t o = ((size_t)(bh * DH + d)) * Sk + s0 + 2 * sp;
        *(uint32_t*)(Vth + o) = hi;
        *(uint32_t*)(Vtl + o) = lo;
    }
}

// ==================== attention: HMMA flash, cp.async double-buffered ============
#define AKH 0
#define AKL 9216
#define AVH 18432
#define AVL 27648
#define AMS 36864
#define ABUF 37120
#define ASMEM (2 * ABUF)

__global__ __launch_bounds__(256, 1) void attn_hmma(
    const float* __restrict__ Q,
    const __nv_bfloat16* __restrict__ Kh, const __nv_bfloat16* __restrict__ Kl,
    const __nv_bfloat16* __restrict__ Vth, const __nv_bfloat16* __restrict__ Vtl,
    const int* __restrict__ mask, float* __restrict__ O, int Sq, int Sk)
{
    extern __shared__ char sm[];
    const uint32_t sb = smem_u32(sm);
    const int tid = threadIdx.x;
    const int wid = tid >> 5;
    const int lane = tid & 31;
    const int g = lane >> 2;
    const int t = lane & 3;
    const int b = blockIdx.z, h = blockIdx.y;
    const int q0 = blockIdx.x * 128;
    const int bh = b * NH + h;
    const int nt = Sk / 64;

    // ---- per-thread cp.async source/dst precompute ----
    const __nv_bfloat16* tb[4] = {Kh, Kl, Vth, Vtl};
    const char* csrc[8];
    uint32_t cdst[8];
    const uint32_t toff[4] = {AKH, AKL, AVH, AVL};
#pragma unroll
    for (int q = 0; q < 8; q++) {
        int sub = ((q & 1) << 8) | tid;
        int r = sub >> 3, c = sub & 7;
        size_t off = (q < 4) ? ((size_t)(bh * (size_t)Sk + r) * DH + c * 8)
                             : ((size_t)(bh * DH + r) * (size_t)Sk + c * 8);
        csrc[q] = (const char*)(tb[q >> 1] + off);
        cdst[q] = toff[q >> 1] + (uint32_t)(r * 144 + c * 16);
    }
    const char* msrc = (const char*)(mask + (size_t)b * Sk) + tid * 16;

    // issue tile 0 into buf 0
    {
#pragma unroll
        for (int q = 0; q < 8; q++)
            cp16(sb + cdst[q], csrc[q]);
        if (tid < 16) cp16(sb + AMS + tid * 16, msrc);
        asm volatile("cp.async.commit_group;");
    }

    // ---- stage Q into buf1 region, build fragments ----
    float* qs = (float*)(sm + ABUF);
#pragma unroll
    for (int i = 0; i < 8; i++) {
        int f = tid + 256 * i;
        int r = f >> 4, c4 = f & 15;
        float4 v = *(const float4*)(Q + (size_t)(b * Sq + q0 + r) * HS + h * DH + c4 * 4);
        *(float4*)(qs + r * 68 + c4 * 4) = v;
    }
    __syncthreads();

    uint32_t qh[4][4], ql[4][4];
    {
        const int wr = wid * 16;
        const float* q0p = qs + (wr + g) * 68;
        const float* q8p = qs + (wr + g + 8) * 68;
#pragma unroll
        for (int kk = 0; kk < 4; kk++) {
            int c0 = 16 * kk + 2 * t;
            float2 x0 = *(const float2*)(q0p + c0);
            float2 x1 = *(const float2*)(q8p + c0);
            float2 x2 = *(const float2*)(q0p + c0 + 8);
            float2 x3 = *(const float2*)(q8p + c0 + 8);
            float2 xs[4] = {x0, x1, x2, x3};
#pragma unroll
            for (int r = 0; r < 4; r++) {
                uint32_t hi = cvt2(xs[r].y, xs[r].x);
                float f0 = __int_as_float(hi << 16);
                float f1 = __int_as_float(hi & 0xffff0000u);
                qh[kk][r] = hi;
                ql[kk][r] = cvt2(xs[r].y - f1, xs[r].x - f0);
            }
        }
    }
    __syncthreads();

    // issue tile 1 into buf 1
    if (nt > 1) {
#pragma unroll
        for (int q = 0; q < 8; q++)
            cp16(sb + ABUF + cdst[q], csrc[q] + ((q < 4) ? 8192 : 128));
        if (tid < 16) cp16(sb + ABUF + AMS + tid * 16, msrc + 256);
    }
    asm volatile("cp.async.commit_group;");

    // ---- online softmax state ----
    float oacc[8][4];
#pragma unroll
    for (int j = 0; j < 8; j++)
#pragma unroll
        for (int k = 0; k < 4; k++) oacc[j][k] = 0.f;
    float m0 = -1e30f, m1 = -1e30f, l0 = 0.f, l1 = 0.f;

    for (int it = 0; it < nt; it++) {
        if (it + 1 < nt) { asm volatile("cp.async.wait_group 1;"); }
        else             { asm volatile("cp.async.wait_group 0;"); }
        __syncthreads();

        char* buf = sm + (it & 1) * ABUF;
        const int* ms = (const int*)(buf + AMS);

        // ---- S = Q @ K^T (split bf16) ----
        float sacc[8][4];
#pragma unroll
        for (int j = 0; j < 8; j++)
#pragma unroll
            for (int k = 0; k < 4; k++) sacc[j][k] = 0.f;

#pragma unroll
        for (int kk = 0; kk < 4; kk++) {
#pragma unroll
            for (int j = 0; j < 8; j++) {
                int off = (8 * j + g) * 144 + (16 * kk + 2 * t) * 2;
                uint32_t bh2[2], bl2[2];
                bh2[0] = *(const uint32_t*)(buf + AKH + off);
                bh2[1] = *(const uint32_t*)(buf + AKH + off + 16);
                bl2[0] = *(const uint32_t*)(buf + AKL + off);
                bl2[1] = *(const uint32_t*)(buf + AKL + off + 16);
                mma_bf16(sacc[j], qh[kk], bh2);
                mma_bf16(sacc[j], qh[kk], bl2);
                mma_bf16(sacc[j], ql[kk], bh2);
            }
        }

        // ---- softmax (scale + mask + online max/sum), exp2 on FMA pipe ----
        float r0 = -1e30f, r1 = -1e30f;
#pragma unroll
        for (int j = 0; j < 8; j++) {
            int2 mv = *(const int2*)(ms + 8 * j + 2 * t);
            float a0 = mv.x ? 0.f : MASKADD;
            float a1 = mv.y ? 0.f : MASKADD;
            sacc[j][0] = fmaf(sacc[j][0], CSC, a0);
            sacc[j][1] = fmaf(sacc[j][1], CSC, a1);
            sacc[j][2] = fmaf(sacc[j][2], CSC, a0);
            sacc[j][3] = fmaf(sacc[j][3], CSC, a1);
            r0 = fmaxf(r0, fmaxf(sacc[j][0], sacc[j][1]));
            r1 = fmaxf(r1, fmaxf(sacc[j][2], sacc[j][3]));
        }
        r0 = fmaxf(r0, __shfl_xor_sync(0xffffffffu, r0, 1));
        r0 = fmaxf(r0, __shfl_xor_sync(0xffffffffu, r0, 2));
        r1 = fmaxf(r1, __shfl_xor_sync(0xffffffffu, r1, 1));
        r1 = fmaxf(r1, __shfl_xor_sync(0xffffffffu, r1, 2));

        float m0n = fmaxf(m0, r0);
        float m1n = fmaxf(m1, r1);
        float rs0 = exp2p(m0 - m0n);
        float rs1 = exp2p(m1 - m1n);
        m0 = m0n; m1 = m1n;

        float sum0 = 0.f, sum1 = 0.f;
#pragma unroll
        for (int j = 0; j < 8; j++) {
            sacc[j][0] = exp2p(sacc[j][0] - m0);
            sacc[j][1] = exp2p(sacc[j][1] - m0);
            sacc[j][2] = exp2p(sacc[j][2] - m1);
            sacc[j][3] = exp2p(sacc[j][3] - m1);
            sum0 += sacc[j][0] + sacc[j][1];
            sum1 += sacc[j][2] + sacc[j][3];
        }
        sum0 += __shfl_xor_sync(0xffffffffu, sum0, 1);
        sum0 += __shfl_xor_sync(0xffffffffu, sum0, 2);
        sum1 += __shfl_xor_sync(0xffffffffu, sum1, 1);
        sum1 += __shfl_xor_sync(0xffffffffu, sum1, 2);
        l0 = l0 * rs0 + sum0;
        l1 = l1 * rs1 + sum1;

#pragma unroll
        for (int j = 0; j < 8; j++) {
            oacc[j][0] *= rs0; oacc[j][1] *= rs0;
            oacc[j][2] *= rs1; oacc[j][3] *= rs1;
        }

        // ---- pack P into A-fragments (register-only) ----
        uint32_t ph[4][4], pl[4][4];
#pragma unroll
        for (int s = 0; s < 4; s++) {
            const float* pa = sacc[2 * s];
            const float* pb = sacc[2 * s + 1];
            float srcs[4][2] = {{pa[0], pa[1]}, {pa[2], pa[3]}, {pb[0], pb[1]}, {pb[2], pb[3]}};
#pragma unroll
            for (int r = 0; r < 4; r++) {
                uint32_t hi = cvt2(srcs[r][1], srcs[r][0]);
                float f0 = __int_as_float(hi << 16);
                float f1 = __int_as_float(hi & 0xffff0000u);
                ph[s][r] = hi;
                pl[s][r] = cvt2(srcs[r][1] - f1, srcs[r][0] - f0);
            }
        }

        // ---- O += P @ V (split: Ph*Vh + Ph*Vl + Pl*Vh) ----
#pragma unroll
        for (int s = 0; s < 4; s++) {
#pragma unroll
            for (int j = 0; j < 8; j++) {
                int off = (8 * j + g) * 144 + (16 * s + 2 * t) * 2;
                uint32_t vh2[2], vl2[2];
                vh2[0] = *(const uint32_t*)(buf + AVH + off);
                vh2[1] = *(const uint32_t*)(buf + AVH + off + 16);
                vl2[0] = *(const uint32_t*)(buf + AVL + off);
                vl2[1] = *(const uint32_t*)(buf + AVL + off + 16);
                mma_bf16(oacc[j], ph[s], vh2);
                mma_bf16(oacc[j], ph[s], vl2);
                mma_bf16(oacc[j], pl[s], vh2);
            }
        }

        __syncthreads();
        if (it + 2 < nt) {
            size_t kaK = (size_t)(it + 2) * 8192;
            size_t kaV = (size_t)(it + 2) * 128;
            uint32_t db = sb + (it & 1) * ABUF;
#pragma unroll
            for (int q = 0; q < 8; q++)
                cp16(db + cdst[q], csrc[q] + ((q < 4) ? kaK : kaV));
            if (tid < 16) cp16(db + AMS + tid * 16, msrc + (size_t)(it + 2) * 256);
        }
        asm volatile("cp.async.commit_group;");
    }

    // ---- finalize + write ----
    float inv0 = 1.f / l0;
    float inv1 = 1.f / l1;
    int row0 = q0 + wid * 16 + g;
#pragma unroll
    for (int j = 0; j < 8; j++) {
        int col = h * DH + 8 * j + 2 * t;
        *(float2*)(O + (size_t)(b * Sq + row0) * HS + col) =
            make_float2(oacc[j][0] * inv0, oacc[j][1] * inv0);
        *(float2*)(O + (size_t)(b * Sq + row0 + 8) * HS + col) =
            make_float2(oacc[j][2] * inv1, oacc[j][3] * inv1);
    }
}

// ==================== fused residual add + LayerNorm ====================
__global__ __launch_bounds__(256) void add_ln_kernel(
    const float* __restrict__ x, const float* __restrict__ att,
    const float* __restrict__ g, const float* __restrict__ bb,
    float* __restrict__ out)
{
    int row = blockIdx.x;
    int tid = threadIdx.x;
    const float4* x4 = (const float4*)(x + (size_t)row * HS);
    const float4* a4 = (const float4*)(att + (size_t)row * HS);
    float4 xv = x4[tid];
    float4 av = a4[tid];
    float v0 = xv.x + av.x, v1 = xv.y + av.y, v2 = xv.z + av.z, v3 = xv.w + av.w;

    float s = v0 + v1 + v2 + v3;
    float sq = v0 * v0 + v1 * v1 + v2 * v2 + v3 * v3;
#pragma unroll
    for (int off = 16; off > 0; off >>= 1) {
        s  += __shfl_xor_sync(0xffffffffu, s, off);
        sq += __shfl_xor_sync(0xffffffffu, sq, off);
    }
    __shared__ float ss[8], ssq[8];
    int wid = tid >> 5, lane = tid & 31;
    if (lane == 0) { ss[wid] = s; ssq[wid] = sq; }
    __syncthreads();
    s = 0.f; sq = 0.f;
#pragma unroll
    for (int w = 0; w < 8; w++) { s += ss[w]; sq += ssq[w]; }

    float mu = s * (1.f / HS);
    float var = sq * (1.f / HS) - mu * mu;
    float r = rsqrtf(var + 1e-5f);

    float4 gv = ((const float4*)g)[tid];
    float4 bv = ((const float4*)bb)[tid];
    float4 ov = make_float4((v0 - mu) * r * gv.x + bv.x,
                            (v1 - mu) * r * gv.y + bv.y,
                            (v2 - mu) * r * gv.z + bv.z,
                            (v3 - mu) * r * gv.w + bv.w);
    ((float4*)(out + (size_t)row * HS))[tid] = ov;
}

// ==================== launcher ====================
extern "C" void kernel_launch(void* const* d_in, const int* in_sizes, int n_in,
                              void* d_out, int out_size)
{
    (void)in_sizes; (void)n_in; (void)out_size;
    const float* x_c   = (const float*)d_in[0];
    const float* x_e   = (const float*)d_in[1];
    const int*   msk_c = (const int*)d_in[2];
    const int*   msk_e = (const int*)d_in[3];
    const float* W_cq = (const float*)d_in[4];  const float* b_cq = (const float*)d_in[5];
    const float* W_ek = (const float*)d_in[6];  const float* b_ek = (const float*)d_in[7];
    const float* W_ev = (const float*)d_in[8];  const float* b_ev = (const float*)d_in[9];
    const float* W_eq = (const float*)d_in[10]; const float* b_eq = (const float*)d_in[11];
    const float* W_ck = (const float*)d_in[12]; const float* b_ck = (const float*)d_in[13];
    const float* W_cv = (const float*)d_in[14]; const float* b_cv = (const float*)d_in[15];
    const float* ln_g = (const float*)d_in[16]; const float* ln_b = (const float*)d_in[17];
    float* out = (float*)d_out;

    float *Qc, *Kc, *Vc, *Ac, *Qe, *Ke, *Ve, *Ae;
    cudaGetSymbolAddress((void**)&Qc, g_Qc);
    cudaGetSymbolAddress((void**)&Kc, g_Kc);
    cudaGetSymbolAddress((void**)&Vc, g_Vc);
    cudaGetSymbolAddress((void**)&Ac, g_Ac);
    cudaGetSymbolAddress((void**)&Qe, g_Qe);
    cudaGetSymbolAddress((void**)&Ke, g_Ke);
    cudaGetSymbolAddress((void**)&Ve, g_Ve);
    cudaGetSymbolAddress((void**)&Ae, g_Ae);
    __nv_bfloat16 *Keh, *Kel, *Veth, *Vetl, *Kch, *Kcl, *Vcth, *Vctl;
    cudaGetSymbolAddress((void**)&Keh, g_Keh);
    cudaGetSymbolAddress((void**)&Kel, g_Kel);
    cudaGetSymbolAddress((void**)&Veth, g_Veth);
    cudaGetSymbolAddress((void**)&Vetl, g_Vetl);
    cudaGetSymbolAddress((void**)&Kch, g_Kch);
    cudaGetSymbolAddress((void**)&Kcl, g_Kcl);
    cudaGetSymbolAddress((void**)&Vcth, g_Vcth);
    cudaGetSymbolAddress((void**)&Vctl, g_Vctl);

    cudaFuncSetAttribute(gemm_hmma, cudaFuncAttributeMaxDynamicSharedMemorySize, GSMEM);
    cudaFuncSetAttribute(attn_hmma, cudaFuncAttributeMaxDynamicSharedMemorySize, ASMEM);

    const int Mc = B * SC;
    const int Me = B * SE;

    dim3 gc(HS / 128, Mc / 128);
    dim3 ge(HS / 128, Me / 128);
    gemm_hmma<<<gc, 256, GSMEM>>>(x_c, W_cq, b_cq, Qc);
    gemm_hmma<<<gc, 256, GSMEM>>>(x_c, W_ck, b_ck, Kc);
    gemm_hmma<<<gc, 256, GSMEM>>>(x_c, W_cv, b_cv, Vc);
    gemm_hmma<<<ge, 256, GSMEM>>>(x_e, W_ek, b_ek, Ke);
    gemm_hmma<<<ge, 256, GSMEM>>>(x_e, W_ev, b_ev, Ve);
    gemm_hmma<<<ge, 256, GSMEM>>>(x_e, W_eq, b_eq, Qe);

    prep_kv<<<dim3(SC / 64, NH, B), 256>>>(Kc, Vc, Kch, Kcl, Vcth, Vctl, SC);
    prep_kv<<<dim3(SE / 64, NH, B), 256>>>(Ke, Ve, Keh, Kel, Veth, Vetl, SE);

    attn_hmma<<<dim3(SC / 128, NH, B), 256, ASMEM>>>(
        Qc, Keh, Kel, Veth, Vetl, msk_e, Ac, SC, SE);
    attn_hmma<<<dim3(SE / 128, NH, B), 256, ASMEM>>>(
        Qe, Kch, Kcl, Vcth, Vctl, msk_c, Ae, SE, SC);

    add_ln_kernel<<<Mc, 256>>>(x_c, Ac, ln_g, ln_b, out);
    add_ln_kernel<<<Me, 256>>>(x_e, Ae, ln_g, ln_b, out + (size_t)Mc * HS);
}

// round 5
// speedup vs baseline: 3.8040x; 1.3162x over previous
#include <cuda_runtime.h>
#include <cuda_bf16.h>
#include <cuda_fp16.h>
#include <cstdint>

#define HS 1024
#define NH 16
#define DH 64
#define B 4
#define SC 512
#define SE 2048

// -------------------- scratch (device globals; no allocation) --------------------
__device__ float g_QKVc[(size_t)3 * B * SC * HS];   // Qc | Kc | Vc
__device__ float g_QKVe[(size_t)3 * B * SE * HS];   // Qe | Ke | Ve
__device__ float g_Ac[(size_t)B * SC * HS];
__device__ float g_Ae[(size_t)B * SE * HS];
// fp16 preconverted operands
__device__ __align__(256) __half g_xch[(size_t)B * SC * HS];
__device__ __align__(256) __half g_xcl[(size_t)B * SC * HS];
__device__ __align__(256) __half g_xeh[(size_t)B * SE * HS];
__device__ __align__(256) __half g_xel[(size_t)B * SE * HS];
__device__ __align__(256) __half g_Wch[(size_t)3 * HS * HS];   // W_cq|W_ck|W_cv
__device__ __align__(256) __half g_Weh[(size_t)3 * HS * HS];   // W_eq|W_ek|W_ev
// bf16 split K / V-transposed per head (attention operands)
__device__ __align__(256) __nv_bfloat16 g_Keh[(size_t)B * NH * SE * DH];
__device__ __align__(256) __nv_bfloat16 g_Kel[(size_t)B * NH * SE * DH];
__device__ __align__(256) __nv_bfloat16 g_Veth[(size_t)B * NH * SE * DH];
__device__ __align__(256) __nv_bfloat16 g_Vetl[(size_t)B * NH * SE * DH];
__device__ __align__(256) __nv_bfloat16 g_Kch[(size_t)B * NH * SC * DH];
__device__ __align__(256) __nv_bfloat16 g_Kcl[(size_t)B * NH * SC * DH];
__device__ __align__(256) __nv_bfloat16 g_Vcth[(size_t)B * NH * SC * DH];
__device__ __align__(256) __nv_bfloat16 g_Vctl[(size_t)B * NH * SC * DH];

// ==================== helpers ====================
__device__ __forceinline__ void mma_bf16(float* d, const uint32_t* a, const uint32_t* b) {
    asm volatile(
        "mma.sync.aligned.m16n8k16.row.col.f32.bf16.bf16.f32 "
        "{%0,%1,%2,%3}, {%4,%5,%6,%7}, {%8,%9}, {%0,%1,%2,%3};"
        : "+f"(d[0]), "+f"(d[1]), "+f"(d[2]), "+f"(d[3])
        : "r"(a[0]), "r"(a[1]), "r"(a[2]), "r"(a[3]), "r"(b[0]), "r"(b[1]));
}

__device__ __forceinline__ void mma_f16(float* d, const uint32_t* a, const uint32_t* b) {
    asm volatile(
        "mma.sync.aligned.m16n8k16.row.col.f32.f16.f16.f32 "
        "{%0,%1,%2,%3}, {%4,%5,%6,%7}, {%8,%9}, {%0,%1,%2,%3};"
        : "+f"(d[0]), "+f"(d[1]), "+f"(d[2]), "+f"(d[3])
        : "r"(a[0]), "r"(a[1]), "r"(a[2]), "r"(a[3]), "r"(b[0]), "r"(b[1]));
}

__device__ __forceinline__ uint32_t pack_bf16(__nv_bfloat16 a, __nv_bfloat16 b) {
    __nv_bfloat162 p(a, b);
    return *(uint32_t*)&p;
}

__device__ __forceinline__ uint32_t cvt2(float hi, float lo) {
    uint32_t r;
    asm("cvt.rn.satfinite.bf16x2.f32 %0, %1, %2;" : "=r"(r) : "f"(hi), "f"(lo));
    return r;
}

__device__ __forceinline__ void cvt_split(float4 v, uint2& hi, uint2& lo) {
    __nv_bfloat16 h0 = __float2bfloat16(v.x);
    __nv_bfloat16 h1 = __float2bfloat16(v.y);
    __nv_bfloat16 h2 = __float2bfloat16(v.z);
    __nv_bfloat16 h3 = __float2bfloat16(v.w);
    __nv_bfloat16 l0 = __float2bfloat16(v.x - __bfloat162float(h0));
    __nv_bfloat16 l1 = __float2bfloat16(v.y - __bfloat162float(h1));
    __nv_bfloat16 l2 = __float2bfloat16(v.z - __bfloat162float(h2));
    __nv_bfloat16 l3 = __float2bfloat16(v.w - __bfloat162float(h3));
    hi = make_uint2(pack_bf16(h0, h1), pack_bf16(h2, h3));
    lo = make_uint2(pack_bf16(l0, l1), pack_bf16(l2, l3));
}

__device__ __forceinline__ uint32_t packh2(float a, float b) {
    __half2 h = __floats2half2_rn(a, b);
    return *(uint32_t*)&h;
}

__device__ __forceinline__ uint32_t smem_u32(const void* p) {
    uint32_t a;
    asm("{ .reg .u64 t; cvta.to.shared.u64 t, %1; cvt.u32.u64 %0, t; }" : "=r"(a) : "l"(p));
    return a;
}

__device__ __forceinline__ void cp16(uint32_t dst, const void* src) {
    asm volatile("cp.async.cg.shared.global [%0], [%1], 16;" :: "r"(dst), "l"(src));
}

// exp2 on the FMA pipe: deg-5 Taylor on [-0.5, 0.5], max rel err ~2.4e-6
__device__ __forceinline__ float exp2p(float d) {
    d = fmaxf(d, -126.f);
    int i = __float2int_rn(d);
    float fr = d - (float)i;
    float p = 1.3333558146e-3f;
    p = fmaf(p, fr, 9.6181291076e-3f);
    p = fmaf(p, fr, 5.5504108664e-2f);
    p = fmaf(p, fr, 2.4022650696e-1f);
    p = fmaf(p, fr, 6.9314718056e-1f);
    p = fmaf(p, fr, 1.0f);
    return p * __int_as_float((i + 127) << 23);
}

#define CSC 0.1803368801111694f   // log2(e)/8
#define MASKADD (-24000.0f)

// ==================== convert kernels ====================
__global__ __launch_bounds__(256) void cvt_split_h(
    const float* __restrict__ s, __half* __restrict__ h, __half* __restrict__ l)
{
    int i = blockIdx.x * 256 + threadIdx.x;
    float4 v = ((const float4*)s)[i];
    __half hx = __float2half_rn(v.x);
    __half hy = __float2half_rn(v.y);
    __half hz = __float2half_rn(v.z);
    __half hw = __float2half_rn(v.w);
    float lx = v.x - __half2float(hx);
    float ly = v.y - __half2float(hy);
    float lz = v.z - __half2float(hz);
    float lw = v.w - __half2float(hw);
    __half2 h01(hx, hy), h23(hz, hw);
    ((uint2*)h)[i] = make_uint2(*(uint32_t*)&h01, *(uint32_t*)&h23);
    ((uint2*)l)[i] = make_uint2(packh2(lx, ly), packh2(lz, lw));
}

__global__ __launch_bounds__(256) void cvt_h(
    const float* __restrict__ s, __half* __restrict__ h)
{
    int i = blockIdx.x * 256 + threadIdx.x;
    float4 v = ((const float4*)s)[i];
    ((uint2*)h)[i] = make_uint2(packh2(v.x, v.y), packh2(v.z, v.w));
}

// ==================== GEMM: C[z][M,1024] = A[M,1024] @ Wz^T + bias_z ============
// fp16 2-term (Ah+Al)·Wh. CTA 128x128, 128 threads, warp tile 64x64, k-chunk 32,
// cp.async double-buffered, preconverted fp16 operands. grid = (8, M/128, 3).
#define G_RS    80
#define G_TILE  (128 * G_RS)          // 10240
#define G_AH    0
#define G_AL    (1 * G_TILE)
#define G_BH    (2 * G_TILE)
#define G_STAGE (3 * G_TILE)          // 30720
#define G_SMEM  (2 * G_STAGE)         // 61440

__global__ __launch_bounds__(128, 2) void gemm_f16(
    const __half* __restrict__ Ah, const __half* __restrict__ Al,
    const __half* __restrict__ Wh,
    const float* __restrict__ bq, const float* __restrict__ bk,
    const float* __restrict__ bv,
    float* __restrict__ Cbase, int M)
{
    extern __shared__ char smem[];
    const uint32_t sb = smem_u32(smem);
    const int tid = threadIdx.x;
    const int wid = tid >> 5;
    const int lane = tid & 31;
    const int g = lane >> 2;
    const int t = lane & 3;
    const int wm = wid >> 1;
    const int wn = wid & 1;
    const int bm = blockIdx.y * 128;
    const int bn = blockIdx.x * 128;
    const int z = blockIdx.z;

    const __half* Wz = Wh + ((size_t)z << 20);
    float* C = Cbase + (size_t)z * M * HS;
    const float* bias = (z == 0) ? bq : ((z == 1) ? bk : bv);

    // precompute cp.async src/dst (12 chunks of 16B per thread per stage)
    const char* csrc[12];
    uint32_t cdst[12];
#pragma unroll
    for (int q = 0; q < 12; q++) {
        int f = q * 128 + tid;
        int tile = f >> 9;
        int idx = f & 511;
        int r = idx >> 2, col = idx & 3;
        cdst[q] = (uint32_t)(tile * G_TILE + r * G_RS + col * 16);
        if (tile == 0)      csrc[q] = (const char*)(Ah + (size_t)(bm + r) * HS + col * 8);
        else if (tile == 1) csrc[q] = (const char*)(Al + (size_t)(bm + r) * HS + col * 8);
        else                csrc[q] = (const char*)(Wz + (size_t)(bn + r) * HS + col * 8);
    }

    // prologue: stages 0,1
#pragma unroll
    for (int st = 0; st < 2; st++) {
        uint32_t db = sb + st * G_STAGE;
#pragma unroll
        for (int q = 0; q < 12; q++)
            cp16(db + cdst[q], csrc[q] + st * 64);
        asm volatile("cp.async.commit_group;");
    }

    float acc[4][8][4];
#pragma unroll
    for (int i = 0; i < 4; i++)
#pragma unroll
        for (int j = 0; j < 8; j++)
#pragma unroll
            for (int k = 0; k < 4; k++) acc[i][j][k] = 0.f;

    const int NC = HS / 32;   // 32 chunks

    for (int c = 0; c < NC; c++) {
        if (c + 1 < NC) { asm volatile("cp.async.wait_group 1;"); }
        else            { asm volatile("cp.async.wait_group 0;"); }
        __syncthreads();

        const char* buf = smem + (c & 1) * G_STAGE;
#pragma unroll
        for (int s = 0; s < 2; s++) {
            const int kb = s * 32 + 4 * t;
            uint32_t ah[4][4], al[4][4];
#pragma unroll
            for (int i = 0; i < 4; i++) {
                int r = wm * 64 + 16 * i + g;
                const char* pa = buf + G_AH + r * G_RS + kb;
                ah[i][0] = *(const uint32_t*)(pa);
                ah[i][1] = *(const uint32_t*)(pa + 8 * G_RS);
                ah[i][2] = *(const uint32_t*)(pa + 16);
                ah[i][3] = *(const uint32_t*)(pa + 8 * G_RS + 16);
                const char* pl = buf + G_AL + r * G_RS + kb;
                al[i][0] = *(const uint32_t*)(pl);
                al[i][1] = *(const uint32_t*)(pl + 8 * G_RS);
                al[i][2] = *(const uint32_t*)(pl + 16);
                al[i][3] = *(const uint32_t*)(pl + 8 * G_RS + 16);
            }
#pragma unroll
            for (int j = 0; j < 8; j++) {
                int nr = wn * 64 + 8 * j + g;
                const char* pb = buf + G_BH + nr * G_RS + kb;
                uint32_t bh[2];
                bh[0] = *(const uint32_t*)(pb);
                bh[1] = *(const uint32_t*)(pb + 16);
#pragma unroll
                for (int i = 0; i < 4; i++) {
                    mma_f16(acc[i][j], ah[i], bh);
                    mma_f16(acc[i][j], al[i], bh);
                }
            }
        }
        __syncthreads();

        if (c + 2 < NC) {
            uint32_t db = sb + (c & 1) * G_STAGE;
            int koff = (c + 2) * 64;
#pragma unroll
            for (int q = 0; q < 12; q++)
                cp16(db + cdst[q], csrc[q] + koff);
        }
        asm volatile("cp.async.commit_group;");
    }

    // epilogue
#pragma unroll
    for (int i = 0; i < 4; i++) {
        int row0 = bm + wm * 64 + 16 * i + g;
#pragma unroll
        for (int j = 0; j < 8; j++) {
            int col = bn + wn * 64 + 8 * j + 2 * t;
            float2 bv2 = *(const float2*)(bias + col);
            *(float2*)(C + (size_t)row0 * HS + col) =
                make_float2(acc[i][j][0] + bv2.x, acc[i][j][1] + bv2.y);
            *(float2*)(C + (size_t)(row0 + 8) * HS + col) =
                make_float2(acc[i][j][2] + bv2.x, acc[i][j][3] + bv2.y);
        }
    }
}

// ==================== K/V prep: fp32 -> split bf16 (K row-major, V transposed) ====
__global__ __launch_bounds__(256) void prep_kv(
    const float* __restrict__ K, const float* __restrict__ V,
    __nv_bfloat16* __restrict__ Kh, __nv_bfloat16* __restrict__ Kl,
    __nv_bfloat16* __restrict__ Vth, __nv_bfloat16* __restrict__ Vtl, int Sk)
{
    __shared__ float vs[64][65];
    const int tid = threadIdx.x;
    const int b = blockIdx.z, h = blockIdx.y;
    const int s0 = blockIdx.x * 64;
    const int bh = b * NH + h;

#pragma unroll
    for (int i = 0; i < 4; i++) {
        int f = tid + 256 * i;
        int r = f >> 4, c4 = f & 15;
        float4 v = *(const float4*)(K + (size_t)(b * Sk + s0 + r) * HS + h * DH + c4 * 4);
        uint2 hi, lo;
        cvt_split(v, hi, lo);
        size_t o = ((size_t)(bh * Sk + s0 + r)) * DH + c4 * 4;
        *(uint2*)(Kh + o) = hi;
        *(uint2*)(Kl + o) = lo;
    }
#pragma unroll
    for (int i = 0; i < 4; i++) {
        int f = tid + 256 * i;
        int r = f >> 4, c4 = f & 15;
        float4 v = *(const float4*)(V + (size_t)(b * Sk + s0 + r) * HS + h * DH + c4 * 4);
        vs[r][c4 * 4 + 0] = v.x;
        vs[r][c4 * 4 + 1] = v.y;
        vs[r][c4 * 4 + 2] = v.z;
        vs[r][c4 * 4 + 3] = v.w;
    }
    __syncthreads();
#pragma unroll
    for (int i = 0; i < 8; i++) {
        int f = tid + 256 * i;
        int d = f >> 5, sp = f & 31;
        float v0 = vs[2 * sp][d], v1 = vs[2 * sp + 1][d];
        uint32_t hi = cvt2(v1, v0);
        float f0 = __int_as_float(hi << 16);
        float f1 = __int_as_float(hi & 0xffff0000u);
        uint32_t lo = cvt2(v1 - f1, v0 - f0);
        size_t o = ((size_t)(bh * DH + d)) * Sk + s0 + 2 * sp;
        *(uint32_t*)(Vth + o) = hi;
        *(uint32_t*)(Vtl + o) = lo;
    }
}

// ==================== attention: HMMA flash, cp.async double-buffered ============
#define AKH 0
#define AKL 9216
#define AVH 18432
#define AVL 27648
#define AMS 36864
#define ABUF 37120
#define ASMEM (2 * ABUF)

__global__ __launch_bounds__(256, 1) void attn_hmma(
    const float* __restrict__ Q,
    const __nv_bfloat16* __restrict__ Kh, const __nv_bfloat16* __restrict__ Kl,
    const __nv_bfloat16* __restrict__ Vth, const __nv_bfloat16* __restrict__ Vtl,
    const int* __restrict__ mask, float* __restrict__ O, int Sq, int Sk)
{
    extern __shared__ char sm[];
    const uint32_t sb = smem_u32(sm);
    const int tid = threadIdx.x;
    const int wid = tid >> 5;
    const int lane = tid & 31;
    const int g = lane >> 2;
    const int t = lane & 3;
    const int b = blockIdx.z, h = blockIdx.y;
    const int q0 = blockIdx.x * 128;
    const int bh = b * NH + h;
    const int nt = Sk / 64;

    const __nv_bfloat16* tb[4] = {Kh, Kl, Vth, Vtl};
    const char* csrc[8];
    uint32_t cdst[8];
    const uint32_t toff[4] = {AKH, AKL, AVH, AVL};
#pragma unroll
    for (int q = 0; q < 8; q++) {
        int sub = ((q & 1) << 8) | tid;
        int r = sub >> 3, c = sub & 7;
        size_t off = (q < 4) ? ((size_t)(bh * (size_t)Sk + r) * DH + c * 8)
                             : ((size_t)(bh * DH + r) * (size_t)Sk + c * 8);
        csrc[q] = (const char*)(tb[q >> 1] + off);
        cdst[q] = toff[q >> 1] + (uint32_t)(r * 144 + c * 16);
    }
    const char* msrc = (const char*)(mask + (size_t)b * Sk) + tid * 16;

    {
#pragma unroll
        for (int q = 0; q < 8; q++)
            cp16(sb + cdst[q], csrc[q]);
        if (tid < 16) cp16(sb + AMS + tid * 16, msrc);
        asm volatile("cp.async.commit_group;");
    }

    float* qs = (float*)(sm + ABUF);
#pragma unroll
    for (int i = 0; i < 8; i++) {
        int f = tid + 256 * i;
        int r = f >> 4, c4 = f & 15;
        float4 v = *(const float4*)(Q + (size_t)(b * Sq + q0 + r) * HS + h * DH + c4 * 4);
        *(float4*)(qs + r * 68 + c4 * 4) = v;
    }
    __syncthreads();

    uint32_t qh[4][4], ql[4][4];
    {
        const int wr = wid * 16;
        const float* q0p = qs + (wr + g) * 68;
        const float* q8p = qs + (wr + g + 8) * 68;
#pragma unroll
        for (int kk = 0; kk < 4; kk++) {
            int c0 = 16 * kk + 2 * t;
            float2 x0 = *(const float2*)(q0p + c0);
            float2 x1 = *(const float2*)(q8p + c0);
            float2 x2 = *(const float2*)(q0p + c0 + 8);
            float2 x3 = *(const float2*)(q8p + c0 + 8);
            float2 xs[4] = {x0, x1, x2, x3};
#pragma unroll
            for (int r = 0; r < 4; r++) {
                uint32_t hi = cvt2(xs[r].y, xs[r].x);
                float f0 = __int_as_float(hi << 16);
                float f1 = __int_as_float(hi & 0xffff0000u);
                qh[kk][r] = hi;
                ql[kk][r] = cvt2(xs[r].y - f1, xs[r].x - f0);
            }
        }
    }
    __syncthreads();

    if (nt > 1) {
#pragma unroll
        for (int q = 0; q < 8; q++)
            cp16(sb + ABUF + cdst[q], csrc[q] + ((q < 4) ? 8192 : 128));
        if (tid < 16) cp16(sb + ABUF + AMS + tid * 16, msrc + 256);
    }
    asm volatile("cp.async.commit_group;");

    float oacc[8][4];
#pragma unroll
    for (int j = 0; j < 8; j++)
#pragma unroll
        for (int k = 0; k < 4; k++) oacc[j][k] = 0.f;
    float m0 = -1e30f, m1 = -1e30f, l0 = 0.f, l1 = 0.f;

    for (int it = 0; it < nt; it++) {
        if (it + 1 < nt) { asm volatile("cp.async.wait_group 1;"); }
        else             { asm volatile("cp.async.wait_group 0;"); }
        __syncthreads();

        char* buf = sm + (it & 1) * ABUF;
        const int* ms = (const int*)(buf + AMS);

        float sacc[8][4];
#pragma unroll
        for (int j = 0; j < 8; j++)
#pragma unroll
            for (int k = 0; k < 4; k++) sacc[j][k] = 0.f;

#pragma unroll
        for (int kk = 0; kk < 4; kk++) {
#pragma unroll
            for (int j = 0; j < 8; j++) {
                int off = (8 * j + g) * 144 + (16 * kk + 2 * t) * 2;
                uint32_t bh2[2], bl2[2];
                bh2[0] = *(const uint32_t*)(buf + AKH + off);
                bh2[1] = *(const uint32_t*)(buf + AKH + off + 16);
                bl2[0] = *(const uint32_t*)(buf + AKL + off);
                bl2[1] = *(const uint32_t*)(buf + AKL + off + 16);
                mma_bf16(sacc[j], qh[kk], bh2);
                mma_bf16(sacc[j], qh[kk], bl2);
                mma_bf16(sacc[j], ql[kk], bh2);
            }
        }

        float r0 = -1e30f, r1 = -1e30f;
#pragma unroll
        for (int j = 0; j < 8; j++) {
            int2 mv = *(const int2*)(ms + 8 * j + 2 * t);
            float a0 = mv.x ? 0.f : MASKADD;
            float a1 = mv.y ? 0.f : MASKADD;
            sacc[j][0] = fmaf(sacc[j][0], CSC, a0);
            sacc[j][1] = fmaf(sacc[j][1], CSC, a1);
            sacc[j][2] = fmaf(sacc[j][2], CSC, a0);
            sacc[j][3] = fmaf(sacc[j][3], CSC, a1);
            r0 = fmaxf(r0, fmaxf(sacc[j][0], sacc[j][1]));
            r1 = fmaxf(r1, fmaxf(sacc[j][2], sacc[j][3]));
        }
        r0 = fmaxf(r0, __shfl_xor_sync(0xffffffffu, r0, 1));
        r0 = fmaxf(r0, __shfl_xor_sync(0xffffffffu, r0, 2));
        r1 = fmaxf(r1, __shfl_xor_sync(0xffffffffu, r1, 1));
        r1 = fmaxf(r1, __shfl_xor_sync(0xffffffffu, r1, 2));

        float m0n = fmaxf(m0, r0);
        float m1n = fmaxf(m1, r1);
        float rs0 = exp2p(m0 - m0n);
        float rs1 = exp2p(m1 - m1n);
        m0 = m0n; m1 = m1n;

        float sum0 = 0.f, sum1 = 0.f;
#pragma unroll
        for (int j = 0; j < 8; j++) {
            sacc[j][0] = exp2p(sacc[j][0] - m0);
            sacc[j][1] = exp2p(sacc[j][1] - m0);
            sacc[j][2] = exp2p(sacc[j][2] - m1);
            sacc[j][3] = exp2p(sacc[j][3] - m1);
            sum0 += sacc[j][0] + sacc[j][1];
            sum1 += sacc[j][2] + sacc[j][3];
        }
        sum0 += __shfl_xor_sync(0xffffffffu, sum0, 1);
        sum0 += __shfl_xor_sync(0xffffffffu, sum0, 2);
        sum1 += __shfl_xor_sync(0xffffffffu, sum1, 1);
        sum1 += __shfl_xor_sync(0xffffffffu, sum1, 2);
        l0 = l0 * rs0 + sum0;
        l1 = l1 * rs1 + sum1;

#pragma unroll
        for (int j = 0; j < 8; j++) {
            oacc[j][0] *= rs0; oacc[j][1] *= rs0;
            oacc[j][2] *= rs1; oacc[j][3] *= rs1;
        }

        uint32_t ph[4][4], pl[4][4];
#pragma unroll
        for (int s = 0; s < 4; s++) {
            const float* pa = sacc[2 * s];
            const float* pb = sacc[2 * s + 1];
            float srcs[4][2] = {{pa[0], pa[1]}, {pa[2], pa[3]}, {pb[0], pb[1]}, {pb[2], pb[3]}};
#pragma unroll
            for (int r = 0; r < 4; r++) {
                uint32_t hi = cvt2(srcs[r][1], srcs[r][0]);
                float f0 = __int_as_float(hi << 16);
                float f1 = __int_as_float(hi & 0xffff0000u);
                ph[s][r] = hi;
                pl[s][r] = cvt2(srcs[r][1] - f1, srcs[r][0] - f0);
            }
        }

#pragma unroll
        for (int s = 0; s < 4; s++) {
#pragma unroll
            for (int j = 0; j < 8; j++) {
                int off = (8 * j + g) * 144 + (16 * s + 2 * t) * 2;
                uint32_t vh2[2], vl2[2];
                vh2[0] = *(const uint32_t*)(buf + AVH + off);
                vh2[1] = *(const uint32_t*)(buf + AVH + off + 16);
                vl2[0] = *(const uint32_t*)(buf + AVL + off);
                vl2[1] = *(const uint32_t*)(buf + AVL + off + 16);
                mma_bf16(oacc[j], ph[s], vh2);
                mma_bf16(oacc[j], ph[s], vl2);
                mma_bf16(oacc[j], pl[s], vh2);
            }
        }

        __syncthreads();
        if (it + 2 < nt) {
            size_t kaK = (size_t)(it + 2) * 8192;
            size_t kaV = (size_t)(it + 2) * 128;
            uint32_t db = sb + (it & 1) * ABUF;
#pragma unroll
            for (int q = 0; q < 8; q++)
                cp16(db + cdst[q], csrc[q] + ((q < 4) ? kaK : kaV));
            if (tid < 16) cp16(db + AMS + tid * 16, msrc + (size_t)(it + 2) * 256);
        }
        asm volatile("cp.async.commit_group;");
    }

    float inv0 = 1.f / l0;
    float inv1 = 1.f / l1;
    int row0 = q0 + wid * 16 + g;
#pragma unroll
    for (int j = 0; j < 8; j++) {
        int col = h * DH + 8 * j + 2 * t;
        *(float2*)(O + (size_t)(b * Sq + row0) * HS + col) =
            make_float2(oacc[j][0] * inv0, oacc[j][1] * inv0);
        *(float2*)(O + (size_t)(b * Sq + row0 + 8) * HS + col) =
            make_float2(oacc[j][2] * inv1, oacc[j][3] * inv1);
    }
}

// ==================== fused residual add + LayerNorm ====================
__global__ __launch_bounds__(256) void add_ln_kernel(
    const float* __restrict__ x, const float* __restrict__ att,
    const float* __restrict__ g, const float* __restrict__ bb,
    float* __restrict__ out)
{
    int row = blockIdx.x;
    int tid = threadIdx.x;
    const float4* x4 = (const float4*)(x + (size_t)row * HS);
    const float4* a4 = (const float4*)(att + (size_t)row * HS);
    float4 xv = x4[tid];
    float4 av = a4[tid];
    float v0 = xv.x + av.x, v1 = xv.y + av.y, v2 = xv.z + av.z, v3 = xv.w + av.w;

    float s = v0 + v1 + v2 + v3;
    float sq = v0 * v0 + v1 * v1 + v2 * v2 + v3 * v3;
#pragma unroll
    for (int off = 16; off > 0; off >>= 1) {
        s  += __shfl_xor_sync(0xffffffffu, s, off);
        sq += __shfl_xor_sync(0xffffffffu, sq, off);
    }
    __shared__ float ss[8], ssq[8];
    int wid = tid >> 5, lane = tid & 31;
    if (lane == 0) { ss[wid] = s; ssq[wid] = sq; }
    __syncthreads();
    s = 0.f; sq = 0.f;
#pragma unroll
    for (int w = 0; w < 8; w++) { s += ss[w]; sq += ssq[w]; }

    float mu = s * (1.f / HS);
    float var = sq * (1.f / HS) - mu * mu;
    float r = rsqrtf(var + 1e-5f);

    float4 gv = ((const float4*)g)[tid];
    float4 bv = ((const float4*)bb)[tid];
    float4 ov = make_float4((v0 - mu) * r * gv.x + bv.x,
                            (v1 - mu) * r * gv.y + bv.y,
                            (v2 - mu) * r * gv.z + bv.z,
                            (v3 - mu) * r * gv.w + bv.w);
    ((float4*)(out + (size_t)row * HS))[tid] = ov;
}

// ==================== launcher ====================
extern "C" void kernel_launch(void* const* d_in, const int* in_sizes, int n_in,
                              void* d_out, int out_size)
{
    (void)in_sizes; (void)n_in; (void)out_size;
    const float* x_c   = (const float*)d_in[0];
    const float* x_e   = (const float*)d_in[1];
    const int*   msk_c = (const int*)d_in[2];
    const int*   msk_e = (const int*)d_in[3];
    const float* W_cq = (const float*)d_in[4];  const float* b_cq = (const float*)d_in[5];
    const float* W_ek = (const float*)d_in[6];  const float* b_ek = (const float*)d_in[7];
    const float* W_ev = (const float*)d_in[8];  const float* b_ev = (const float*)d_in[9];
    const float* W_eq = (const float*)d_in[10]; const float* b_eq = (const float*)d_in[11];
    const float* W_ck = (const float*)d_in[12]; const float* b_ck = (const float*)d_in[13];
    const float* W_cv = (const float*)d_in[14]; const float* b_cv = (const float*)d_in[15];
    const float* ln_g = (const float*)d_in[16]; const float* ln_b = (const float*)d_in[17];
    float* out = (float*)d_out;

    float *QKVc, *QKVe, *Ac, *Ae;
    cudaGetSymbolAddress((void**)&QKVc, g_QKVc);
    cudaGetSymbolAddress((void**)&QKVe, g_QKVe);
    cudaGetSymbolAddress((void**)&Ac, g_Ac);
    cudaGetSymbolAddress((void**)&Ae, g_Ae);
    __half *xch, *xcl, *xeh, *xel, *Wch, *Weh;
    cudaGetSymbolAddress((void**)&xch, g_xch);
    cudaGetSymbolAddress((void**)&xcl, g_xcl);
    cudaGetSymbolAddress((void**)&xeh, g_xeh);
    cudaGetSymbolAddress((void**)&xel, g_xel);
    cudaGetSymbolAddress((void**)&Wch, g_Wch);
    cudaGetSymbolAddress((void**)&Weh, g_Weh);
    __nv_bfloat16 *Keh, *Kel, *Veth, *Vetl, *Kch, *Kcl, *Vcth, *Vctl;
    cudaGetSymbolAddress((void**)&Keh, g_Keh);
    cudaGetSymbolAddress((void**)&Kel, g_Kel);
    cudaGetSymbolAddress((void**)&Veth, g_Veth);
    cudaGetSymbolAddress((void**)&Vetl, g_Vetl);
    cudaGetSymbolAddress((void**)&Kch, g_Kch);
    cudaGetSymbolAddress((void**)&Kcl, g_Kcl);
    cudaGetSymbolAddress((void**)&Vcth, g_Vcth);
    cudaGetSymbolAddress((void**)&Vctl, g_Vctl);

    cudaFuncSetAttribute(gemm_f16, cudaFuncAttributeMaxDynamicSharedMemorySize, G_SMEM);
    cudaFuncSetAttribute(attn_hmma, cudaFuncAttributeMaxDynamicSharedMemorySize, ASMEM);

    const int Mc = B * SC;   // 2048
    const int Me = B * SE;   // 8192
    const int WN4 = (HS * HS) / 4;   // 262144 per weight

    // convert activations (split fp16) and weights (plain fp16)
    cvt_split_h<<<(Mc * HS / 4) / 256, 256>>>(x_c, xch, xcl);
    cvt_split_h<<<(Me * HS / 4) / 256, 256>>>(x_e, xeh, xel);
    cvt_h<<<WN4 / 256, 256>>>(W_cq, Wch);
    cvt_h<<<WN4 / 256, 256>>>(W_ck, Wch + (1u << 20));
    cvt_h<<<WN4 / 256, 256>>>(W_cv, Wch + (2u << 20));
    cvt_h<<<WN4 / 256, 256>>>(W_eq, Weh);
    cvt_h<<<WN4 / 256, 256>>>(W_ek, Weh + (1u << 20));
    cvt_h<<<WN4 / 256, 256>>>(W_ev, Weh + (2u << 20));

    // batched projections: z0=Q, z1=K, z2=V
    gemm_f16<<<dim3(8, Mc / 128, 3), 128, G_SMEM>>>(
        xch, xcl, Wch, b_cq, b_ck, b_cv, QKVc, Mc);
    gemm_f16<<<dim3(8, Me / 128, 3), 128, G_SMEM>>>(
        xeh, xel, Weh, b_eq, b_ek, b_ev, QKVe, Me);

    float* Qc = QKVc;
    float* Kc = QKVc + (size_t)Mc * HS;
    float* Vc = QKVc + (size_t)2 * Mc * HS;
    float* Qe = QKVe;
    float* Ke = QKVe + (size_t)Me * HS;
    float* Ve = QKVe + (size_t)2 * Me * HS;

    prep_kv<<<dim3(SC / 64, NH, B), 256>>>(Kc, Vc, Kch, Kcl, Vcth, Vctl, SC);
    prep_kv<<<dim3(SE / 64, NH, B), 256>>>(Ke, Ve, Keh, Kel, Veth, Vetl, SE);

    attn_hmma<<<dim3(SC / 128, NH, B), 256, ASMEM>>>(
        Qc, Keh, Kel, Veth, Vetl, msk_e, Ac, SC, SE);
    attn_hmma<<<dim3(SE / 128, NH, B), 256, ASMEM>>>(
        Qe, Kch, Kcl, Vcth, Vctl, msk_c, Ae, SE, SC);

    add_ln_kernel<<<Mc, 256>>>(x_c, Ac, ln_g, ln_b, out);
    add_ln_kernel<<<Me, 256>>>(x_e, Ae, ln_g, ln_b, out + (size_t)Mc * HS);
}

// round 6
// speedup vs baseline: 4.4445x; 1.1684x over previous
#include <cuda_runtime.h>
#include <cuda_fp16.h>
#include <cstdint>

#define HS 1024
#define NH 16
#define DH 64
#define B 4
#define SC 512
#define SE 2048

// -------------------- scratch (device globals; no allocation) --------------------
__device__ float g_QKVc[(size_t)3 * B * SC * HS];   // Qc | Kc | Vc
__device__ float g_QKVe[(size_t)3 * B * SE * HS];   // Qe | Ke | Ve
__device__ float g_Ac[(size_t)B * SC * HS];
__device__ float g_Ae[(size_t)B * SE * HS];
// fp16 preconverted GEMM operands
__device__ __align__(256) __half g_xch[(size_t)B * SC * HS];
__device__ __align__(256) __half g_xcl[(size_t)B * SC * HS];
__device__ __align__(256) __half g_xeh[(size_t)B * SE * HS];
__device__ __align__(256) __half g_xel[(size_t)B * SE * HS];
__device__ __align__(256) __half g_Wch[(size_t)3 * HS * HS];   // W_cq|W_ck|W_cv
__device__ __align__(256) __half g_Weh[(size_t)3 * HS * HS];   // W_eq|W_ek|W_ev
// fp16 K / V-transposed per head (attention operands)
__device__ __align__(256) __half g_Ke16[(size_t)B * NH * SE * DH];
__device__ __align__(256) __half g_Vte16[(size_t)B * NH * SE * DH];
__device__ __align__(256) __half g_Kc16[(size_t)B * NH * SC * DH];
__device__ __align__(256) __half g_Vtc16[(size_t)B * NH * SC * DH];

// ==================== helpers ====================
__device__ __forceinline__ void mma_f16(float* d, const uint32_t* a, const uint32_t* b) {
    asm volatile(
        "mma.sync.aligned.m16n8k16.row.col.f32.f16.f16.f32 "
        "{%0,%1,%2,%3}, {%4,%5,%6,%7}, {%8,%9}, {%0,%1,%2,%3};"
        : "+f"(d[0]), "+f"(d[1]), "+f"(d[2]), "+f"(d[3])
        : "r"(a[0]), "r"(a[1]), "r"(a[2]), "r"(a[3]), "r"(b[0]), "r"(b[1]));
}

__device__ __forceinline__ uint32_t packh2(float a, float b) {
    __half2 h = __floats2half2_rn(a, b);
    return *(uint32_t*)&h;
}

// split pair (a,b) into fp16 hi + residual lo fragments
__device__ __forceinline__ void split_h2(float a, float b, uint32_t& hi, uint32_t& lo) {
    __half2 h = __floats2half2_rn(a, b);
    float2 hf = __half22float2(h);
    hi = *(uint32_t*)&h;
    lo = packh2(a - hf.x, b - hf.y);
}

__device__ __forceinline__ uint32_t smem_u32(const void* p) {
    uint32_t a;
    asm("{ .reg .u64 t; cvta.to.shared.u64 t, %1; cvt.u32.u64 %0, t; }" : "=r"(a) : "l"(p));
    return a;
}

__device__ __forceinline__ void cp16(uint32_t dst, const void* src) {
    asm volatile("cp.async.cg.shared.global [%0], [%1], 16;" :: "r"(dst), "l"(src));
}

// exp2 on the FMA pipe: deg-5 Taylor on [-0.5, 0.5], max rel err ~2.4e-6
__device__ __forceinline__ float exp2p(float d) {
    d = fmaxf(d, -126.f);
    int i = __float2int_rn(d);
    float fr = d - (float)i;
    float p = 1.3333558146e-3f;
    p = fmaf(p, fr, 9.6181291076e-3f);
    p = fmaf(p, fr, 5.5504108664e-2f);
    p = fmaf(p, fr, 2.4022650696e-1f);
    p = fmaf(p, fr, 6.9314718056e-1f);
    p = fmaf(p, fr, 1.0f);
    return p * __int_as_float((i + 127) << 23);
}

#define CSC 0.1803368801111694f   // log2(e)/8
#define MASKADD (-24000.0f)

// ==================== convert kernels ====================
__global__ __launch_bounds__(256) void cvt_split_h(
    const float* __restrict__ s, __half* __restrict__ h, __half* __restrict__ l)
{
    int i = blockIdx.x * 256 + threadIdx.x;
    float4 v = ((const float4*)s)[i];
    uint32_t h01, l01, h23, l23;
    split_h2(v.x, v.y, h01, l01);
    split_h2(v.z, v.w, h23, l23);
    ((uint2*)h)[i] = make_uint2(h01, h23);
    ((uint2*)l)[i] = make_uint2(l01, l23);
}

// all 6 weights in one launch: y = 0..2 -> claim (Wch), 3..5 -> evidence (Weh)
__global__ __launch_bounds__(256) void cvt_w6(
    const float* __restrict__ s0, const float* __restrict__ s1,
    const float* __restrict__ s2, const float* __restrict__ s3,
    const float* __restrict__ s4, const float* __restrict__ s5,
    __half* __restrict__ dc, __half* __restrict__ de)
{
    int z = blockIdx.y;
    const float* srcs[6] = {s0, s1, s2, s3, s4, s5};
    const float* s = srcs[z];
    __half* d = (z < 3) ? (dc + ((size_t)z << 20)) : (de + ((size_t)(z - 3) << 20));
    int i = blockIdx.x * 256 + threadIdx.x;
    float4 v = ((const float4*)s)[i];
    ((uint2*)d)[i] = make_uint2(packh2(v.x, v.y), packh2(v.z, v.w));
}

// ==================== GEMM: all 6 projections in one launch ====================
// fp16 2-term (Ah+Al)*Wh. CTA 128x128, 128 threads, warp tile 64x64, k-chunk 32,
// 3-stage cp.async pipeline. grid = (8, 64, 6): z<3 evidence Q/K/V, z>=3 claim.
#define G_RS    80
#define G_TILE  (128 * G_RS)          // 10240
#define G_AH    0
#define G_AL    (1 * G_TILE)
#define G_BH    (2 * G_TILE)
#define G_STAGE (3 * G_TILE)          // 30720
#define G_SMEM  (3 * G_STAGE)         // 92160

__global__ __launch_bounds__(128, 2) void gemm_f16(
    const __half* __restrict__ xeh, const __half* __restrict__ xel,
    const __half* __restrict__ Weh,
    const __half* __restrict__ xch, const __half* __restrict__ xcl,
    const __half* __restrict__ Wch,
    const float* __restrict__ beq, const float* __restrict__ bek,
    const float* __restrict__ bev,
    const float* __restrict__ bcq, const float* __restrict__ bck,
    const float* __restrict__ bcv,
    float* __restrict__ Ce, float* __restrict__ Cc)
{
    const int z = blockIdx.z;
    const __half *Ah, *Al, *Wz;
    float* C;
    const float* bias;
    if (z < 3) {
        Ah = xeh; Al = xel;
        Wz = Weh + ((size_t)z << 20);
        C = Ce + (size_t)z * (B * SE) * HS;
        bias = (z == 0) ? beq : ((z == 1) ? bek : bev);
    } else {
        if (blockIdx.y >= (B * SC) / 128) return;
        int zz = z - 3;
        Ah = xch; Al = xcl;
        Wz = Wch + ((size_t)zz << 20);
        C = Cc + (size_t)zz * (B * SC) * HS;
        bias = (zz == 0) ? bcq : ((zz == 1) ? bck : bcv);
    }

    extern __shared__ char smem[];
    const uint32_t sb = smem_u32(smem);
    const int tid = threadIdx.x;
    const int wid = tid >> 5;
    const int lane = tid & 31;
    const int g = lane >> 2;
    const int t = lane & 3;
    const int wm = wid >> 1;
    const int wn = wid & 1;
    const int bm = blockIdx.y * 128;
    const int bn = blockIdx.x * 128;

    // cp.async src/dst (12 chunks of 16B per thread per stage)
    const char* csrc[12];
    uint32_t cdst[12];
#pragma unroll
    for (int q = 0; q < 12; q++) {
        int f = q * 128 + tid;
        int tile = f >> 9;
        int idx = f & 511;
        int r = idx >> 2, col = idx & 3;
        cdst[q] = (uint32_t)(tile * G_TILE + r * G_RS + col * 16);
        if (tile == 0)      csrc[q] = (const char*)(Ah + (size_t)(bm + r) * HS + col * 8);
        else if (tile == 1) csrc[q] = (const char*)(Al + (size_t)(bm + r) * HS + col * 8);
        else                csrc[q] = (const char*)(Wz + (size_t)(bn + r) * HS + col * 8);
    }

    const int NC = HS / 32;   // 32 chunks

    // prologue: stages 0..2
#pragma unroll
    for (int st = 0; st < 3; st++) {
        uint32_t db = sb + st * G_STAGE;
#pragma unroll
        for (int q = 0; q < 12; q++)
            cp16(db + cdst[q], csrc[q] + st * 64);
        asm volatile("cp.async.commit_group;");
    }

    float acc[4][8][4];
#pragma unroll
    for (int i = 0; i < 4; i++)
#pragma unroll
        for (int j = 0; j < 8; j++)
#pragma unroll
            for (int k = 0; k < 4; k++) acc[i][j][k] = 0.f;

    for (int c = 0; c < NC; c++) {
        asm volatile("cp.async.wait_group 2;");
        __syncthreads();

        const char* buf = smem + (c % 3) * G_STAGE;
#pragma unroll
        for (int s = 0; s < 2; s++) {
            const int kb = s * 32 + 4 * t;
            uint32_t ah[4][4], al[4][4];
#pragma unroll
            for (int i = 0; i < 4; i++) {
                int r = wm * 64 + 16 * i + g;
                const char* pa = buf + G_AH + r * G_RS + kb;
                ah[i][0] = *(const uint32_t*)(pa);
                ah[i][1] = *(const uint32_t*)(pa + 8 * G_RS);
                ah[i][2] = *(const uint32_t*)(pa + 16);
                ah[i][3] = *(const uint32_t*)(pa + 8 * G_RS + 16);
                const char* pl = buf + G_AL + r * G_RS + kb;
                al[i][0] = *(const uint32_t*)(pl);
                al[i][1] = *(const uint32_t*)(pl + 8 * G_RS);
                al[i][2] = *(const uint32_t*)(pl + 16);
                al[i][3] = *(const uint32_t*)(pl + 8 * G_RS + 16);
            }
#pragma unroll
            for (int j = 0; j < 8; j++) {
                int nr = wn * 64 + 8 * j + g;
                const char* pb = buf + G_BH + nr * G_RS + kb;
                uint32_t bh[2];
                bh[0] = *(const uint32_t*)(pb);
                bh[1] = *(const uint32_t*)(pb + 16);
#pragma unroll
                for (int i = 0; i < 4; i++) {
                    mma_f16(acc[i][j], ah[i], bh);
                    mma_f16(acc[i][j], al[i], bh);
                }
            }
        }
        __syncthreads();

        if (c + 3 < NC) {
            uint32_t db = sb + ((c + 3) % 3) * G_STAGE;
            int koff = (c + 3) * 64;
#pragma unroll
            for (int q = 0; q < 12; q++)
                cp16(db + cdst[q], csrc[q] + koff);
        }
        asm volatile("cp.async.commit_group;");
    }

    // epilogue
#pragma unroll
    for (int i = 0; i < 4; i++) {
        int row0 = bm + wm * 64 + 16 * i + g;
#pragma unroll
        for (int j = 0; j < 8; j++) {
            int col = bn + wn * 64 + 8 * j + 2 * t;
            float2 bv2 = *(const float2*)(bias + col);
            *(float2*)(C + (size_t)row0 * HS + col) =
                make_float2(acc[i][j][0] + bv2.x, acc[i][j][1] + bv2.y);
            *(float2*)(C + (size_t)(row0 + 8) * HS + col) =
                make_float2(acc[i][j][2] + bv2.x, acc[i][j][3] + bv2.y);
        }
    }
}

// ==================== K/V prep: fp32 -> fp16 (K row-major, V transposed) =========
__global__ __launch_bounds__(256) void prep_kv(
    const float* __restrict__ K, const float* __restrict__ V,
    __half* __restrict__ Kh, __half* __restrict__ Vth, int Sk)
{
    __shared__ float vs[64][65];
    const int tid = threadIdx.x;
    const int b = blockIdx.z, h = blockIdx.y;
    const int s0 = blockIdx.x * 64;
    const int bh = b * NH + h;

#pragma unroll
    for (int i = 0; i < 4; i++) {
        int f = tid + 256 * i;
        int r = f >> 4, c4 = f & 15;
        float4 v = *(const float4*)(K + (size_t)(b * Sk + s0 + r) * HS + h * DH + c4 * 4);
        size_t o = ((size_t)(bh * Sk + s0 + r)) * DH + c4 * 4;
        *(uint2*)(Kh + o) = make_uint2(packh2(v.x, v.y), packh2(v.z, v.w));
    }
#pragma unroll
    for (int i = 0; i < 4; i++) {
        int f = tid + 256 * i;
        int r = f >> 4, c4 = f & 15;
        float4 v = *(const float4*)(V + (size_t)(b * Sk + s0 + r) * HS + h * DH + c4 * 4);
        vs[r][c4 * 4 + 0] = v.x;
        vs[r][c4 * 4 + 1] = v.y;
        vs[r][c4 * 4 + 2] = v.z;
        vs[r][c4 * 4 + 3] = v.w;
    }
    __syncthreads();
#pragma unroll
    for (int i = 0; i < 8; i++) {
        int f = tid + 256 * i;
        int d = f >> 5, sp = f & 31;
        float v0 = vs[2 * sp][d], v1 = vs[2 * sp + 1][d];
        size_t o = ((size_t)(bh * DH + d)) * Sk + s0 + 2 * sp;
        *(uint32_t*)(Vth + o) = packh2(v0, v1);
    }
}

// ==================== attention: both directions in ONE launch ====================
// fp16 2-term: (Qh+Ql)*K for scores, (Ph+Pl)*V for output.
#define AK    0
#define AV    9216
#define AMS   18432
#define ABUF  18688
#define ASMEM (2 * ABUF)   // 37376

__global__ __launch_bounds__(256, 1) void attn_all(
    const float* __restrict__ Qc, const __half* __restrict__ Ke,
    const __half* __restrict__ Vte, const int* __restrict__ me,
    float* __restrict__ Ac,
    const float* __restrict__ Qe, const __half* __restrict__ Kc,
    const __half* __restrict__ Vtc, const int* __restrict__ mc,
    float* __restrict__ Ae)
{
    extern __shared__ char sm[];
    const uint32_t sb = smem_u32(sm);
    const int tid = threadIdx.x;
    const int wid = tid >> 5;
    const int lane = tid & 31;
    const int g = lane >> 2;
    const int t = lane & 3;
    const int b = blockIdx.z, h = blockIdx.y;
    const int bx = blockIdx.x;
    const int bh = b * NH + h;

    const float* Q;
    const __half* K;
    const __half* Vt;
    const int* mask;
    float* O;
    int Sq, Sk, q0;
    if (bx < SC / 128) {
        Q = Qc; K = Ke; Vt = Vte; mask = me; O = Ac;
        Sq = SC; Sk = SE; q0 = bx * 128;
    } else {
        Q = Qe; K = Kc; Vt = Vtc; mask = mc; O = Ae;
        Sq = SE; Sk = SC; q0 = (bx - SC / 128) * 128;
    }
    const int nt = Sk / 64;

    // cp.async plan: 2 K chunks + 2 V chunks (16B each) per thread per tile
    const char* csrc[4];
    uint32_t cdst[4];
#pragma unroll
    for (int q = 0; q < 4; q++) {
        int sub = ((q & 1) << 8) | tid;
        int r = sub >> 3, c = sub & 7;
        if (q < 2) {
            csrc[q] = (const char*)(K + (size_t)(bh * (size_t)Sk + r) * DH + c * 8);
            cdst[q] = AK + (uint32_t)(r * 144 + c * 16);
        } else {
            csrc[q] = (const char*)(Vt + (size_t)(bh * DH + r) * (size_t)Sk + c * 8);
            cdst[q] = AV + (uint32_t)(r * 144 + c * 16);
        }
    }
    const char* msrc = (const char*)(mask + (size_t)b * Sk) + tid * 16;

    // issue tiles 0 and 1
    {
#pragma unroll
        for (int q = 0; q < 4; q++)
            cp16(sb + cdst[q], csrc[q]);
        if (tid < 16) cp16(sb + AMS + tid * 16, msrc);
        asm volatile("cp.async.commit_group;");
    }
    if (nt > 1) {
#pragma unroll
        for (int q = 0; q < 4; q++)
            cp16(sb + ABUF + cdst[q], csrc[q] + ((q < 2) ? 8192 : 128));
        if (tid < 16) cp16(sb + ABUF + AMS + tid * 16, msrc + 256);
    }
    asm volatile("cp.async.commit_group;");

    // Q fragments straight from gmem (one-time), split fp16
    uint32_t qh[4][4], ql[4][4];
    {
        const float* qp0 = Q + (size_t)(b * Sq + q0 + wid * 16 + g) * HS + h * DH;
        const float* qp8 = qp0 + 8 * HS;
#pragma unroll
        for (int kk = 0; kk < 4; kk++) {
            int c0 = 16 * kk + 2 * t;
            float2 x0 = *(const float2*)(qp0 + c0);
            float2 x1 = *(const float2*)(qp8 + c0);
            float2 x2 = *(const float2*)(qp0 + c0 + 8);
            float2 x3 = *(const float2*)(qp8 + c0 + 8);
            split_h2(x0.x, x0.y, qh[kk][0], ql[kk][0]);
            split_h2(x1.x, x1.y, qh[kk][1], ql[kk][1]);
            split_h2(x2.x, x2.y, qh[kk][2], ql[kk][2]);
            split_h2(x3.x, x3.y, qh[kk][3], ql[kk][3]);
        }
    }

    float oacc[8][4];
#pragma unroll
    for (int j = 0; j < 8; j++)
#pragma unroll
        for (int k = 0; k < 4; k++) oacc[j][k] = 0.f;
    float m0 = -1e30f, m1 = -1e30f, l0 = 0.f, l1 = 0.f;

    for (int it = 0; it < nt; it++) {
        if (it + 1 < nt) { asm volatile("cp.async.wait_group 1;"); }
        else             { asm volatile("cp.async.wait_group 0;"); }
        __syncthreads();

        char* buf = sm + (it & 1) * ABUF;
        const int* ms = (const int*)(buf + AMS);

        // ---- S = Q @ K^T ----
        float sacc[8][4];
#pragma unroll
        for (int j = 0; j < 8; j++)
#pragma unroll
            for (int k = 0; k < 4; k++) sacc[j][k] = 0.f;

#pragma unroll
        for (int kk = 0; kk < 4; kk++) {
#pragma unroll
            for (int j = 0; j < 8; j++) {
                int off = (8 * j + g) * 144 + (16 * kk + 2 * t) * 2;
                uint32_t kh2[2];
                kh2[0] = *(const uint32_t*)(buf + AK + off);
                kh2[1] = *(const uint32_t*)(buf + AK + off + 16);
                mma_f16(sacc[j], qh[kk], kh2);
                mma_f16(sacc[j], ql[kk], kh2);
            }
        }

        // ---- softmax ----
        float r0 = -1e30f, r1 = -1e30f;
#pragma unroll
        for (int j = 0; j < 8; j++) {
            int2 mv = *(const int2*)(ms + 8 * j + 2 * t);
            float a0 = mv.x ? 0.f : MASKADD;
            float a1 = mv.y ? 0.f : MASKADD;
            sacc[j][0] = fmaf(sacc[j][0], CSC, a0);
            sacc[j][1] = fmaf(sacc[j][1], CSC, a1);
            sacc[j][2] = fmaf(sacc[j][2], CSC, a0);
            sacc[j][3] = fmaf(sacc[j][3], CSC, a1);
            r0 = fmaxf(r0, fmaxf(sacc[j][0], sacc[j][1]));
            r1 = fmaxf(r1, fmaxf(sacc[j][2], sacc[j][3]));
        }
        r0 = fmaxf(r0, __shfl_xor_sync(0xffffffffu, r0, 1));
        r0 = fmaxf(r0, __shfl_xor_sync(0xffffffffu, r0, 2));
        r1 = fmaxf(r1, __shfl_xor_sync(0xffffffffu, r1, 1));
        r1 = fmaxf(r1, __shfl_xor_sync(0xffffffffu, r1, 2));

        float m0n = fmaxf(m0, r0);
        float m1n = fmaxf(m1, r1);
        float rs0 = exp2p(m0 - m0n);
        float rs1 = exp2p(m1 - m1n);
        m0 = m0n; m1 = m1n;

        float sum0 = 0.f, sum1 = 0.f;
#pragma unroll
        for (int j = 0; j < 8; j++) {
            sacc[j][0] = exp2p(sacc[j][0] - m0);
            sacc[j][1] = exp2p(sacc[j][1] - m0);
            sacc[j][2] = exp2p(sacc[j][2] - m1);
            sacc[j][3] = exp2p(sacc[j][3] - m1);
            sum0 += sacc[j][0] + sacc[j][1];
            sum1 += sacc[j][2] + sacc[j][3];
        }
        sum0 += __shfl_xor_sync(0xffffffffu, sum0, 1);
        sum0 += __shfl_xor_sync(0xffffffffu, sum0, 2);
        sum1 += __shfl_xor_sync(0xffffffffu, sum1, 1);
        sum1 += __shfl_xor_sync(0xffffffffu, sum1, 2);
        l0 = l0 * rs0 + sum0;
        l1 = l1 * rs1 + sum1;

#pragma unroll
        for (int j = 0; j < 8; j++) {
            oacc[j][0] *= rs0; oacc[j][1] *= rs0;
            oacc[j][2] *= rs1; oacc[j][3] *= rs1;
        }

        // ---- pack P into split fp16 A-fragments ----
        uint32_t ph[4][4], pl[4][4];
#pragma unroll
        for (int s = 0; s < 4; s++) {
            const float* pa = sacc[2 * s];
            const float* pb = sacc[2 * s + 1];
            split_h2(pa[0], pa[1], ph[s][0], pl[s][0]);
            split_h2(pa[2], pa[3], ph[s][1], pl[s][1]);
            split_h2(pb[0], pb[1], ph[s][2], pl[s][2]);
            split_h2(pb[2], pb[3], ph[s][3], pl[s][3]);
        }

        // ---- O += P @ V ----
#pragma unroll
        for (int s = 0; s < 4; s++) {
#pragma unroll
            for (int j = 0; j < 8; j++) {
                int off = (8 * j + g) * 144 + (16 * s + 2 * t) * 2;
                uint32_t vh2[2];
                vh2[0] = *(const uint32_t*)(buf + AV + off);
                vh2[1] = *(const uint32_t*)(buf + AV + off + 16);
                mma_f16(oacc[j], ph[s], vh2);
                mma_f16(oacc[j], pl[s], vh2);
            }
        }

        __syncthreads();
        if (it + 2 < nt) {
            size_t kaK = (size_t)(it + 2) * 8192;
            size_t kaV = (size_t)(it + 2) * 128;
            uint32_t db = sb + (it & 1) * ABUF;
#pragma unroll
            for (int q = 0; q < 4; q++)
                cp16(db + cdst[q], csrc[q] + ((q < 2) ? kaK : kaV));
            if (tid < 16) cp16(db + AMS + tid * 16, msrc + (size_t)(it + 2) * 256);
        }
        asm volatile("cp.async.commit_group;");
    }

    float inv0 = 1.f / l0;
    float inv1 = 1.f / l1;
    int row0 = q0 + wid * 16 + g;
#pragma unroll
    for (int j = 0; j < 8; j++) {
        int col = h * DH + 8 * j + 2 * t;
        *(float2*)(O + (size_t)(b * Sq + row0) * HS + col) =
            make_float2(oacc[j][0] * inv0, oacc[j][1] * inv0);
        *(float2*)(O + (size_t)(b * Sq + row0 + 8) * HS + col) =
            make_float2(oacc[j][2] * inv1, oacc[j][3] * inv1);
    }
}

// ==================== fused residual add + LayerNorm ====================
__global__ __launch_bounds__(256) void add_ln_kernel(
    const float* __restrict__ x, const float* __restrict__ att,
    const float* __restrict__ g, const float* __restrict__ bb,
    float* __restrict__ out)
{
    int row = blockIdx.x;
    int tid = threadIdx.x;
    const float4* x4 = (const float4*)(x + (size_t)row * HS);
    const float4* a4 = (const float4*)(att + (size_t)row * HS);
    float4 xv = x4[tid];
    float4 av = a4[tid];
    float v0 = xv.x + av.x, v1 = xv.y + av.y, v2 = xv.z + av.z, v3 = xv.w + av.w;

    float s = v0 + v1 + v2 + v3;
    float sq = v0 * v0 + v1 * v1 + v2 * v2 + v3 * v3;
#pragma unroll
    for (int off = 16; off > 0; off >>= 1) {
        s  += __shfl_xor_sync(0xffffffffu, s, off);
        sq += __shfl_xor_sync(0xffffffffu, sq, off);
    }
    __shared__ float ss[8], ssq[8];
    int wid = tid >> 5, lane = tid & 31;
    if (lane == 0) { ss[wid] = s; ssq[wid] = sq; }
    __syncthreads();
    s = 0.f; sq = 0.f;
#pragma unroll
    for (int w = 0; w < 8; w++) { s += ss[w]; sq += ssq[w]; }

    float mu = s * (1.f / HS);
    float var = sq * (1.f / HS) - mu * mu;
    float r = rsqrtf(var + 1e-5f);

    float4 gv = ((const float4*)g)[tid];
    float4 bv = ((const float4*)bb)[tid];
    float4 ov = make_float4((v0 - mu) * r * gv.x + bv.x,
                            (v1 - mu) * r * gv.y + bv.y,
                            (v2 - mu) * r * gv.z + bv.z,
                            (v3 - mu) * r * gv.w + bv.w);
    ((float4*)(out + (size_t)row * HS))[tid] = ov;
}

// ==================== launcher ====================
extern "C" void kernel_launch(void* const* d_in, const int* in_sizes, int n_in,
                              void* d_out, int out_size)
{
    (void)in_sizes; (void)n_in; (void)out_size;
    const float* x_c   = (const float*)d_in[0];
    const float* x_e   = (const float*)d_in[1];
    const int*   msk_c = (const int*)d_in[2];
    const int*   msk_e = (const int*)d_in[3];
    const float* W_cq = (const float*)d_in[4];  const float* b_cq = (const float*)d_in[5];
    const float* W_ek = (const float*)d_in[6];  const float* b_ek = (const float*)d_in[7];
    const float* W_ev = (const float*)d_in[8];  const float* b_ev = (const float*)d_in[9];
    const float* W_eq = (const float*)d_in[10]; const float* b_eq = (const float*)d_in[11];
    const float* W_ck = (const float*)d_in[12]; const float* b_ck = (const float*)d_in[13];
    const float* W_cv = (const float*)d_in[14]; const float* b_cv = (const float*)d_in[15];
    const float* ln_g = (const float*)d_in[16]; const float* ln_b = (const float*)d_in[17];
    float* out = (float*)d_out;

    float *QKVc, *QKVe, *Ac, *Ae;
    cudaGetSymbolAddress((void**)&QKVc, g_QKVc);
    cudaGetSymbolAddress((void**)&QKVe, g_QKVe);
    cudaGetSymbolAddress((void**)&Ac, g_Ac);
    cudaGetSymbolAddress((void**)&Ae, g_Ae);
    __half *xch, *xcl, *xeh, *xel, *Wch, *Weh;
    cudaGetSymbolAddress((void**)&xch, g_xch);
    cudaGetSymbolAddress((void**)&xcl, g_xcl);
    cudaGetSymbolAddress((void**)&xeh, g_xeh);
    cudaGetSymbolAddress((void**)&xel, g_xel);
    cudaGetSymbolAddress((void**)&Wch, g_Wch);
    cudaGetSymbolAddress((void**)&Weh, g_Weh);
    __half *Ke16, *Vte16, *Kc16, *Vtc16;
    cudaGetSymbolAddress((void**)&Ke16, g_Ke16);
    cudaGetSymbolAddress((void**)&Vte16, g_Vte16);
    cudaGetSymbolAddress((void**)&Kc16, g_Kc16);
    cudaGetSymbolAddress((void**)&Vtc16, g_Vtc16);

    cudaFuncSetAttribute(gemm_f16, cudaFuncAttributeMaxDynamicSharedMemorySize, G_SMEM);
    cudaFuncSetAttribute(attn_all, cudaFuncAttributeMaxDynamicSharedMemorySize, ASMEM);

    const int Mc = B * SC;   // 2048
    const int Me = B * SE;   // 8192
    const int WN4 = (HS * HS) / 4;

    // converts
    cvt_split_h<<<(Mc * HS / 4) / 256, 256>>>(x_c, xch, xcl);
    cvt_split_h<<<(Me * HS / 4) / 256, 256>>>(x_e, xeh, xel);
    cvt_w6<<<dim3(WN4 / 256, 6), 256>>>(W_cq, W_ck, W_cv, W_eq, W_ek, W_ev, Wch, Weh);

    // all 6 projections
    gemm_f16<<<dim3(8, Me / 128, 6), 128, G_SMEM>>>(
        xeh, xel, Weh, xch, xcl, Wch,
        b_eq, b_ek, b_ev, b_cq, b_ck, b_cv,
        QKVe, QKVc);

    float* Qc = QKVc;
    float* Kc = QKVc + (size_t)Mc * HS;
    float* Vc = QKVc + (size_t)2 * Mc * HS;
    float* Qe = QKVe;
    float* Ke = QKVe + (size_t)Me * HS;
    float* Ve = QKVe + (size_t)2 * Me * HS;

    prep_kv<<<dim3(SC / 64, NH, B), 256>>>(Kc, Vc, Kc16, Vtc16, SC);
    prep_kv<<<dim3(SE / 64, NH, B), 256>>>(Ke, Ve, Ke16, Vte16, SE);

    // both attention directions in one launch
    attn_all<<<dim3(SC / 128 + SE / 128, NH, B), 256, ASMEM>>>(
        Qc, Ke16, Vte16, msk_e, Ac,
        Qe, Kc16, Vtc16, msk_c, Ae);

    add_ln_kernel<<<Mc, 256>>>(x_c, Ac, ln_g, ln_b, out);
    add_ln_kernel<<<Me, 256>>>(x_e, Ae, ln_g, ln_b, out + (size_t)Mc * HS);
}

// round 7
// speedup vs baseline: 6.8482x; 1.5408x over previous
#include <cuda_runtime.h>
#include <cuda_fp16.h>
#include <cstdint>

#define HS 1024
#define NH 16
#define DH 64
#define B 4
#define SC 512
#define SE 2048

// -------------------- scratch (device globals; no allocation) --------------------
__device__ float g_QKVc[(size_t)3 * B * SC * HS];   // Qc | Kc | Vc
__device__ float g_QKVe[(size_t)3 * B * SE * HS];   // Qe | Ke | Ve
__device__ float g_Ac[(size_t)B * SC * HS];
__device__ float g_Ae[(size_t)B * SE * HS];
// fp16 preconverted GEMM operands
__device__ __align__(256) __half g_xch[(size_t)B * SC * HS];
__device__ __align__(256) __half g_xeh[(size_t)B * SE * HS];
__device__ __align__(256) __half g_Wch[(size_t)3 * HS * HS];   // W_cq|W_ck|W_cv
__device__ __align__(256) __half g_Weh[(size_t)3 * HS * HS];   // W_eq|W_ek|W_ev
// fp16 K / V-transposed per head (attention operands)
__device__ __align__(256) __half g_Ke16[(size_t)B * NH * SE * DH];
__device__ __align__(256) __half g_Vte16[(size_t)B * NH * SE * DH];
__device__ __align__(256) __half g_Kc16[(size_t)B * NH * SC * DH];
__device__ __align__(256) __half g_Vtc16[(size_t)B * NH * SC * DH];

// ==================== helpers ====================
__device__ __forceinline__ void mma_f16(float* d, const uint32_t* a, const uint32_t* b) {
    asm volatile(
        "mma.sync.aligned.m16n8k16.row.col.f32.f16.f16.f32 "
        "{%0,%1,%2,%3}, {%4,%5,%6,%7}, {%8,%9}, {%0,%1,%2,%3};"
        : "+f"(d[0]), "+f"(d[1]), "+f"(d[2]), "+f"(d[3])
        : "r"(a[0]), "r"(a[1]), "r"(a[2]), "r"(a[3]), "r"(b[0]), "r"(b[1]));
}

__device__ __forceinline__ uint32_t packh2(float a, float b) {
    __half2 h = __floats2half2_rn(a, b);
    return *(uint32_t*)&h;
}

__device__ __forceinline__ uint32_t smem_u32(const void* p) {
    uint32_t a;
    asm("{ .reg .u64 t; cvta.to.shared.u64 t, %1; cvt.u32.u64 %0, t; }" : "=r"(a) : "l"(p));
    return a;
}

__device__ __forceinline__ void cp16(uint32_t dst, const void* src) {
    asm volatile("cp.async.cg.shared.global [%0], [%1], 16;" :: "r"(dst), "l"(src));
}

// exp2 on the FMA pipe: deg-5 Taylor on [-0.5, 0.5], max rel err ~2.4e-6
__device__ __forceinline__ float exp2p(float d) {
    d = fmaxf(d, -126.f);
    int i = __float2int_rn(d);
    float fr = d - (float)i;
    float p = 1.3333558146e-3f;
    p = fmaf(p, fr, 9.6181291076e-3f);
    p = fmaf(p, fr, 5.5504108664e-2f);
    p = fmaf(p, fr, 2.4022650696e-1f);
    p = fmaf(p, fr, 6.9314718056e-1f);
    p = fmaf(p, fr, 1.0f);
    return p * __int_as_float((i + 127) << 23);
}

#define CSC 0.1803368801111694f   // log2(e)/8
#define MASKADD (-24000.0f)

// ==================== merged convert: 6 weights + 2 activations ====================
// grid.x blocks of 256 threads; each thread converts one float4.
// blocks [0,6144): weights (1024 blocks each); [6144,8192): x_c; [8192,16384): x_e
__global__ __launch_bounds__(256) void cvt_all(
    const float* __restrict__ Wcq, const float* __restrict__ Wck,
    const float* __restrict__ Wcv, const float* __restrict__ Weq,
    const float* __restrict__ Wek, const float* __restrict__ Wev,
    const float* __restrict__ xc, const float* __restrict__ xe,
    __half* __restrict__ dWc, __half* __restrict__ dWe,
    __half* __restrict__ dxc, __half* __restrict__ dxe)
{
    int bid = blockIdx.x;
    const float* s;
    __half* d;
    int i;
    if (bid < 6144) {
        int z = bid >> 10;
        const float* Ws[6] = {Wcq, Wck, Wcv, Weq, Wek, Wev};
        s = Ws[z];
        d = (z < 3) ? (dWc + ((size_t)z << 20)) : (dWe + ((size_t)(z - 3) << 20));
        i = (bid & 1023) * 256 + threadIdx.x;
    } else if (bid < 8192) {
        s = xc; d = dxc;
        i = (bid - 6144) * 256 + threadIdx.x;
    } else {
        s = xe; d = dxe;
        i = (bid - 8192) * 256 + threadIdx.x;
    }
    float4 v = ((const float4*)s)[i];
    ((uint2*)d)[i] = make_uint2(packh2(v.x, v.y), packh2(v.z, v.w));
}

// ==================== GEMM: all 6 projections, 1-term fp16 ====================
// CTA 128x128, 128 threads, warp tile 64x64, k-chunk 32, 3-stage cp.async.
// grid = (8, 64, 6): z<3 evidence Q/K/V, z>=3 claim Q/K/V.
#define G_RS    80
#define G_TILE  (128 * G_RS)          // 10240
#define G_AH    0
#define G_BH    (1 * G_TILE)
#define G_STAGE (2 * G_TILE)          // 20480
#define G_SMEM  (3 * G_STAGE)         // 61440

__global__ __launch_bounds__(128, 2) void gemm_f16(
    const __half* __restrict__ xeh, const __half* __restrict__ Weh,
    const __half* __restrict__ xch, const __half* __restrict__ Wch,
    const float* __restrict__ beq, const float* __restrict__ bek,
    const float* __restrict__ bev,
    const float* __restrict__ bcq, const float* __restrict__ bck,
    const float* __restrict__ bcv,
    float* __restrict__ Ce, float* __restrict__ Cc)
{
    const int z = blockIdx.z;
    const __half *Ah, *Wz;
    float* C;
    const float* bias;
    if (z < 3) {
        Ah = xeh;
        Wz = Weh + ((size_t)z << 20);
        C = Ce + (size_t)z * (B * SE) * HS;
        bias = (z == 0) ? beq : ((z == 1) ? bek : bev);
    } else {
        if (blockIdx.y >= (B * SC) / 128) return;
        int zz = z - 3;
        Ah = xch;
        Wz = Wch + ((size_t)zz << 20);
        C = Cc + (size_t)zz * (B * SC) * HS;
        bias = (zz == 0) ? bcq : ((zz == 1) ? bck : bcv);
    }

    extern __shared__ char smem[];
    const uint32_t sb = smem_u32(smem);
    const int tid = threadIdx.x;
    const int wid = tid >> 5;
    const int lane = tid & 31;
    const int g = lane >> 2;
    const int t = lane & 3;
    const int wm = wid >> 1;
    const int wn = wid & 1;
    const int bm = blockIdx.y * 128;
    const int bn = blockIdx.x * 128;

    // cp.async src/dst: 8 chunks of 16B per thread per stage (A + W tiles)
    const char* csrc[8];
    uint32_t cdst[8];
#pragma unroll
    for (int q = 0; q < 8; q++) {
        int f = q * 128 + tid;
        int tile = f >> 9;
        int idx = f & 511;
        int r = idx >> 2, col = idx & 3;
        cdst[q] = (uint32_t)(tile * G_TILE + r * G_RS + col * 16);
        if (tile == 0) csrc[q] = (const char*)(Ah + (size_t)(bm + r) * HS + col * 8);
        else           csrc[q] = (const char*)(Wz + (size_t)(bn + r) * HS + col * 8);
    }

    const int NC = HS / 32;   // 32 chunks

    // prologue: stages 0..2
#pragma unroll
    for (int st = 0; st < 3; st++) {
        uint32_t db = sb + st * G_STAGE;
#pragma unroll
        for (int q = 0; q < 8; q++)
            cp16(db + cdst[q], csrc[q] + st * 64);
        asm volatile("cp.async.commit_group;");
    }

    float acc[4][8][4];
#pragma unroll
    for (int i = 0; i < 4; i++)
#pragma unroll
        for (int j = 0; j < 8; j++)
#pragma unroll
            for (int k = 0; k < 4; k++) acc[i][j][k] = 0.f;

    for (int c = 0; c < NC; c++) {
        asm volatile("cp.async.wait_group 2;");
        __syncthreads();

        const char* buf = smem + (c % 3) * G_STAGE;
#pragma unroll
        for (int s = 0; s < 2; s++) {
            const int kb = s * 32 + 4 * t;
            uint32_t ah[4][4];
#pragma unroll
            for (int i = 0; i < 4; i++) {
                int r = wm * 64 + 16 * i + g;
                const char* pa = buf + G_AH + r * G_RS + kb;
                ah[i][0] = *(const uint32_t*)(pa);
                ah[i][1] = *(const uint32_t*)(pa + 8 * G_RS);
                ah[i][2] = *(const uint32_t*)(pa + 16);
                ah[i][3] = *(const uint32_t*)(pa + 8 * G_RS + 16);
            }
#pragma unroll
            for (int j = 0; j < 8; j++) {
                int nr = wn * 64 + 8 * j + g;
                const char* pb = buf + G_BH + nr * G_RS + kb;
                uint32_t bh[2];
                bh[0] = *(const uint32_t*)(pb);
                bh[1] = *(const uint32_t*)(pb + 16);
#pragma unroll
                for (int i = 0; i < 4; i++)
                    mma_f16(acc[i][j], ah[i], bh);
            }
        }
        __syncthreads();

        if (c + 3 < NC) {
            uint32_t db = sb + ((c + 3) % 3) * G_STAGE;
            int koff = (c + 3) * 64;
#pragma unroll
            for (int q = 0; q < 8; q++)
                cp16(db + cdst[q], csrc[q] + koff);
        }
        asm volatile("cp.async.commit_group;");
    }

    // epilogue
#pragma unroll
    for (int i = 0; i < 4; i++) {
        int row0 = bm + wm * 64 + 16 * i + g;
#pragma unroll
        for (int j = 0; j < 8; j++) {
            int col = bn + wn * 64 + 8 * j + 2 * t;
            float2 bv2 = *(const float2*)(bias + col);
            *(float2*)(C + (size_t)row0 * HS + col) =
                make_float2(acc[i][j][0] + bv2.x, acc[i][j][1] + bv2.y);
            *(float2*)(C + (size_t)(row0 + 8) * HS + col) =
                make_float2(acc[i][j][2] + bv2.x, acc[i][j][3] + bv2.y);
        }
    }
}

// ==================== K/V prep (merged): fp32 -> fp16, V transposed ==============
// grid.x: [0,8) claim tiles, [8,40) evidence tiles
__global__ __launch_bounds__(256) void prep_all(
    const float* __restrict__ Kc, const float* __restrict__ Vc,
    __half* __restrict__ Kc16, __half* __restrict__ Vtc16,
    const float* __restrict__ Ke, const float* __restrict__ Ve,
    __half* __restrict__ Ke16, __half* __restrict__ Vte16)
{
    __shared__ float vs[64][65];
    const int tid = threadIdx.x;
    const int b = blockIdx.z, h = blockIdx.y;
    const int bh = b * NH + h;

    const float *K, *V;
    __half *Kh, *Vth;
    int Sk, s0;
    if (blockIdx.x < SC / 64) {
        K = Kc; V = Vc; Kh = Kc16; Vth = Vtc16; Sk = SC;
        s0 = blockIdx.x * 64;
    } else {
        K = Ke; V = Ve; Kh = Ke16; Vth = Vte16; Sk = SE;
        s0 = (blockIdx.x - SC / 64) * 64;
    }

#pragma unroll
    for (int i = 0; i < 4; i++) {
        int f = tid + 256 * i;
        int r = f >> 4, c4 = f & 15;
        float4 v = *(const float4*)(K + (size_t)(b * Sk + s0 + r) * HS + h * DH + c4 * 4);
        size_t o = ((size_t)(bh * Sk + s0 + r)) * DH + c4 * 4;
        *(uint2*)(Kh + o) = make_uint2(packh2(v.x, v.y), packh2(v.z, v.w));
    }
#pragma unroll
    for (int i = 0; i < 4; i++) {
        int f = tid + 256 * i;
        int r = f >> 4, c4 = f & 15;
        float4 v = *(const float4*)(V + (size_t)(b * Sk + s0 + r) * HS + h * DH + c4 * 4);
        vs[r][c4 * 4 + 0] = v.x;
        vs[r][c4 * 4 + 1] = v.y;
        vs[r][c4 * 4 + 2] = v.z;
        vs[r][c4 * 4 + 3] = v.w;
    }
    __syncthreads();
#pragma unroll
    for (int i = 0; i < 8; i++) {
        int f = tid + 256 * i;
        int d = f >> 5, sp = f & 31;
        float v0 = vs[2 * sp][d], v1 = vs[2 * sp + 1][d];
        size_t o = ((size_t)(bh * DH + d)) * Sk + s0 + 2 * sp;
        *(uint32_t*)(Vth + o) = packh2(v0, v1);
    }
}

// ==================== attention: 1-term fp16, max-free softmax ====================
#define AK    0
#define AV    9216
#define AMS   18432
#define ABUF  18688
#define ASMEM (2 * ABUF)   // 37376

__global__ __launch_bounds__(256, 1) void attn_all(
    const float* __restrict__ Qc, const __half* __restrict__ Ke,
    const __half* __restrict__ Vte, const int* __restrict__ me,
    float* __restrict__ Ac,
    const float* __restrict__ Qe, const __half* __restrict__ Kc,
    const __half* __restrict__ Vtc, const int* __restrict__ mc,
    float* __restrict__ Ae)
{
    extern __shared__ char sm[];
    const uint32_t sb = smem_u32(sm);
    const int tid = threadIdx.x;
    const int wid = tid >> 5;
    const int lane = tid & 31;
    const int g = lane >> 2;
    const int t = lane & 3;
    const int b = blockIdx.z, h = blockIdx.y;
    const int bx = blockIdx.x;
    const int bh = b * NH + h;

    const float* Q;
    const __half* K;
    const __half* Vt;
    const int* mask;
    float* O;
    int Sq, Sk, q0;
    if (bx < SC / 128) {
        Q = Qc; K = Ke; Vt = Vte; mask = me; O = Ac;
        Sq = SC; Sk = SE; q0 = bx * 128;
    } else {
        Q = Qe; K = Kc; Vt = Vtc; mask = mc; O = Ae;
        Sq = SE; Sk = SC; q0 = (bx - SC / 128) * 128;
    }
    const int nt = Sk / 64;

    // cp.async plan: 2 K chunks + 2 V chunks (16B each) per thread per tile
    const char* csrc[4];
    uint32_t cdst[4];
#pragma unroll
    for (int q = 0; q < 4; q++) {
        int sub = ((q & 1) << 8) | tid;
        int r = sub >> 3, c = sub & 7;
        if (q < 2) {
            csrc[q] = (const char*)(K + (size_t)(bh * (size_t)Sk + r) * DH + c * 8);
            cdst[q] = AK + (uint32_t)(r * 144 + c * 16);
        } else {
            csrc[q] = (const char*)(Vt + (size_t)(bh * DH + r) * (size_t)Sk + c * 8);
            cdst[q] = AV + (uint32_t)(r * 144 + c * 16);
        }
    }
    const char* msrc = (const char*)(mask + (size_t)b * Sk) + tid * 16;

    // issue tiles 0 and 1
    {
#pragma unroll
        for (int q = 0; q < 4; q++)
            cp16(sb + cdst[q], csrc[q]);
        if (tid < 16) cp16(sb + AMS + tid * 16, msrc);
        asm volatile("cp.async.commit_group;");
    }
    if (nt > 1) {
#pragma unroll
        for (int q = 0; q < 4; q++)
            cp16(sb + ABUF + cdst[q], csrc[q] + ((q < 2) ? 8192 : 128));
        if (tid < 16) cp16(sb + ABUF + AMS + tid * 16, msrc + 256);
    }
    asm volatile("cp.async.commit_group;");

    // Q fragments from gmem, pre-scaled by CSC, 1-term fp16
    uint32_t qh[4][4];
    {
        const float* qp0 = Q + (size_t)(b * Sq + q0 + wid * 16 + g) * HS + h * DH;
        const float* qp8 = qp0 + 8 * HS;
#pragma unroll
        for (int kk = 0; kk < 4; kk++) {
            int c0 = 16 * kk + 2 * t;
            float2 x0 = *(const float2*)(qp0 + c0);
            float2 x1 = *(const float2*)(qp8 + c0);
            float2 x2 = *(const float2*)(qp0 + c0 + 8);
            float2 x3 = *(const float2*)(qp8 + c0 + 8);
            qh[kk][0] = packh2(x0.x * CSC, x0.y * CSC);
            qh[kk][1] = packh2(x1.x * CSC, x1.y * CSC);
            qh[kk][2] = packh2(x2.x * CSC, x2.y * CSC);
            qh[kk][3] = packh2(x3.x * CSC, x3.y * CSC);
        }
    }

    float oacc[8][4];
#pragma unroll
    for (int j = 0; j < 8; j++)
#pragma unroll
        for (int k = 0; k < 4; k++) oacc[j][k] = 0.f;
    float l0 = 0.f, l1 = 0.f;

    for (int it = 0; it < nt; it++) {
        if (it + 1 < nt) { asm volatile("cp.async.wait_group 1;"); }
        else             { asm volatile("cp.async.wait_group 0;"); }
        __syncthreads();

        char* buf = sm + (it & 1) * ABUF;
        const int* ms = (const int*)(buf + AMS);

        // ---- S = Q @ K^T (already log2-scaled via Q prescale) ----
        float sacc[8][4];
#pragma unroll
        for (int j = 0; j < 8; j++)
#pragma unroll
            for (int k = 0; k < 4; k++) sacc[j][k] = 0.f;

#pragma unroll
        for (int kk = 0; kk < 4; kk++) {
#pragma unroll
            for (int j = 0; j < 8; j++) {
                int off = (8 * j + g) * 144 + (16 * kk + 2 * t) * 2;
                uint32_t kh2[2];
                kh2[0] = *(const uint32_t*)(buf + AK + off);
                kh2[1] = *(const uint32_t*)(buf + AK + off + 16);
                mma_f16(sacc[j], qh[kk], kh2);
            }
        }

        // ---- max-free softmax: p = exp2(s + mask), no running max needed ----
        // |s| <= ||q||*||k||*CSC ~ 5 << 127, so exp2 cannot overflow.
#pragma unroll
        for (int j = 0; j < 8; j++) {
            int2 mv = *(const int2*)(ms + 8 * j + 2 * t);
            float a0 = mv.x ? 0.f : MASKADD;
            float a1 = mv.y ? 0.f : MASKADD;
            sacc[j][0] = exp2p(sacc[j][0] + a0);
            sacc[j][1] = exp2p(sacc[j][1] + a1);
            sacc[j][2] = exp2p(sacc[j][2] + a0);
            sacc[j][3] = exp2p(sacc[j][3] + a1);
            l0 += sacc[j][0] + sacc[j][1];
            l1 += sacc[j][2] + sacc[j][3];
        }

        // ---- pack P into fp16 A-fragments (register-only) ----
        uint32_t ph[4][4];
#pragma unroll
        for (int s = 0; s < 4; s++) {
            const float* pa = sacc[2 * s];
            const float* pb = sacc[2 * s + 1];
            ph[s][0] = packh2(pa[0], pa[1]);
            ph[s][1] = packh2(pa[2], pa[3]);
            ph[s][2] = packh2(pb[0], pb[1]);
            ph[s][3] = packh2(pb[2], pb[3]);
        }

        // ---- O += P @ V ----
#pragma unroll
        for (int s = 0; s < 4; s++) {
#pragma unroll
            for (int j = 0; j < 8; j++) {
                int off = (8 * j + g) * 144 + (16 * s + 2 * t) * 2;
                uint32_t vh2[2];
                vh2[0] = *(const uint32_t*)(buf + AV + off);
                vh2[1] = *(const uint32_t*)(buf + AV + off + 16);
                mma_f16(oacc[j], ph[s], vh2);
            }
        }

        __syncthreads();
        if (it + 2 < nt) {
            size_t kaK = (size_t)(it + 2) * 8192;
            size_t kaV = (size_t)(it + 2) * 128;
            uint32_t db = sb + (it & 1) * ABUF;
#pragma unroll
            for (int q = 0; q < 4; q++)
                cp16(db + cdst[q], csrc[q] + ((q < 2) ? kaK : kaV));
            if (tid < 16) cp16(db + AMS + tid * 16, msrc + (size_t)(it + 2) * 256);
        }
        asm volatile("cp.async.commit_group;");
    }

    // final row-sum reduce across the lane quad, then normalize + write
    l0 += __shfl_xor_sync(0xffffffffu, l0, 1);
    l0 += __shfl_xor_sync(0xffffffffu, l0, 2);
    l1 += __shfl_xor_sync(0xffffffffu, l1, 1);
    l1 += __shfl_xor_sync(0xffffffffu, l1, 2);
    float inv0 = 1.f / l0;
    float inv1 = 1.f / l1;
    int row0 = q0 + wid * 16 + g;
#pragma unroll
    for (int j = 0; j < 8; j++) {
        int col = h * DH + 8 * j + 2 * t;
        *(float2*)(O + (size_t)(b * Sq + row0) * HS + col) =
            make_float2(oacc[j][0] * inv0, oacc[j][1] * inv0);
        *(float2*)(O + (size_t)(b * Sq + row0 + 8) * HS + col) =
            make_float2(oacc[j][2] * inv1, oacc[j][3] * inv1);
    }
}

// ==================== fused residual add + LayerNorm (merged) ====================
__global__ __launch_bounds__(256) void add_ln_all(
    const float* __restrict__ xc, const float* __restrict__ Ac,
    const float* __restrict__ xe, const float* __restrict__ Ae,
    const float* __restrict__ g, const float* __restrict__ bb,
    float* __restrict__ out)
{
    int row = blockIdx.x;
    const float *x, *att;
    if (row < B * SC) { x = xc + (size_t)row * HS; att = Ac + (size_t)row * HS; }
    else {
        int r = row - B * SC;
        x = xe + (size_t)r * HS; att = Ae + (size_t)r * HS;
    }
    int tid = threadIdx.x;
    float4 xv = ((const float4*)x)[tid];
    float4 av = ((const float4*)att)[tid];
    float v0 = xv.x + av.x, v1 = xv.y + av.y, v2 = xv.z + av.z, v3 = xv.w + av.w;

    float s = v0 + v1 + v2 + v3;
    float sq = v0 * v0 + v1 * v1 + v2 * v2 + v3 * v3;
#pragma unroll
    for (int off = 16; off > 0; off >>= 1) {
        s  += __shfl_xor_sync(0xffffffffu, s, off);
        sq += __shfl_xor_sync(0xffffffffu, sq, off);
    }
    __shared__ float ss[8], ssq[8];
    int wid = tid >> 5, lane = tid & 31;
    if (lane == 0) { ss[wid] = s; ssq[wid] = sq; }
    __syncthreads();
    s = 0.f; sq = 0.f;
#pragma unroll
    for (int w = 0; w < 8; w++) { s += ss[w]; sq += ssq[w]; }

    float mu = s * (1.f / HS);
    float var = sq * (1.f / HS) - mu * mu;
    float r = rsqrtf(var + 1e-5f);

    float4 gv = ((const float4*)g)[tid];
    float4 bv = ((const float4*)bb)[tid];
    float4 ov = make_float4((v0 - mu) * r * gv.x + bv.x,
                            (v1 - mu) * r * gv.y + bv.y,
                            (v2 - mu) * r * gv.z + bv.z,
                            (v3 - mu) * r * gv.w + bv.w);
    ((float4*)(out + (size_t)row * HS))[tid] = ov;
}

// ==================== launcher ====================
extern "C" void kernel_launch(void* const* d_in, const int* in_sizes, int n_in,
                              void* d_out, int out_size)
{
    (void)in_sizes; (void)n_in; (void)out_size;
    const float* x_c   = (const float*)d_in[0];
    const float* x_e   = (const float*)d_in[1];
    const int*   msk_c = (const int*)d_in[2];
    const int*   msk_e = (const int*)d_in[3];
    const float* W_cq = (const float*)d_in[4];  const float* b_cq = (const float*)d_in[5];
    const float* W_ek = (const float*)d_in[6];  const float* b_ek = (const float*)d_in[7];
    const float* W_ev = (const float*)d_in[8];  const float* b_ev = (const float*)d_in[9];
    const float* W_eq = (const float*)d_in[10]; const float* b_eq = (const float*)d_in[11];
    const float* W_ck = (const float*)d_in[12]; const float* b_ck = (const float*)d_in[13];
    const float* W_cv = (const float*)d_in[14]; const float* b_cv = (const float*)d_in[15];
    const float* ln_g = (const float*)d_in[16]; const float* ln_b = (const float*)d_in[17];
    float* out = (float*)d_out;

    float *QKVc, *QKVe, *Ac, *Ae;
    cudaGetSymbolAddress((void**)&QKVc, g_QKVc);
    cudaGetSymbolAddress((void**)&QKVe, g_QKVe);
    cudaGetSymbolAddress((void**)&Ac, g_Ac);
    cudaGetSymbolAddress((void**)&Ae, g_Ae);
    __half *xch, *xeh, *Wch, *Weh;
    cudaGetSymbolAddress((void**)&xch, g_xch);
    cudaGetSymbolAddress((void**)&xeh, g_xeh);
    cudaGetSymbolAddress((void**)&Wch, g_Wch);
    cudaGetSymbolAddress((void**)&Weh, g_Weh);
    __half *Ke16, *Vte16, *Kc16, *Vtc16;
    cudaGetSymbolAddress((void**)&Ke16, g_Ke16);
    cudaGetSymbolAddress((void**)&Vte16, g_Vte16);
    cudaGetSymbolAddress((void**)&Kc16, g_Kc16);
    cudaGetSymbolAddress((void**)&Vtc16, g_Vtc16);

    cudaFuncSetAttribute(gemm_f16, cudaFuncAttributeMaxDynamicSharedMemorySize, G_SMEM);
    cudaFuncSetAttribute(attn_all, cudaFuncAttributeMaxDynamicSharedMemorySize, ASMEM);

    const int Mc = B * SC;   // 2048
    const int Me = B * SE;   // 8192

    // one convert launch: 6 weights + 2 activation tensors
    cvt_all<<<16384, 256>>>(W_cq, W_ck, W_cv, W_eq, W_ek, W_ev, x_c, x_e,
                            Wch, Weh, xch, xeh);

    // all 6 projections
    gemm_f16<<<dim3(8, Me / 128, 6), 128, G_SMEM>>>(
        xeh, Weh, xch, Wch,
        b_eq, b_ek, b_ev, b_cq, b_ck, b_cv,
        QKVe, QKVc);

    float* Qc = QKVc;
    float* Kc = QKVc + (size_t)Mc * HS;
    float* Vc = QKVc + (size_t)2 * Mc * HS;
    float* Qe = QKVe;
    float* Ke = QKVe + (size_t)Me * HS;
    float* Ve = QKVe + (size_t)2 * Me * HS;

    // one prep launch: claim + evidence K/V
    prep_all<<<dim3(SC / 64 + SE / 64, NH, B), 256>>>(
        Kc, Vc, Kc16, Vtc16, Ke, Ve, Ke16, Vte16);

    // both attention directions in one launch
    attn_all<<<dim3(SC / 128 + SE / 128, NH, B), 256, ASMEM>>>(
        Qc, Ke16, Vte16, msk_e, Ac,
        Qe, Kc16, Vtc16, msk_c, Ae);

    // one LN launch: claim rows then evidence rows (matches output packing)
    add_ln_all<<<Mc + Me, 256>>>(x_c, Ac, x_e, Ae, ln_g, ln_b, out);
}

// round 8
// speedup vs baseline: 7.4482x; 1.0876x over previous
#include <cuda_runtime.h>
#include <cuda_fp16.h>
#include <cstdint>

#define HS 1024
#define NH 16
#define DH 64
#define B 4
#define SC 512
#define SE 2048

// -------------------- scratch (device globals; no allocation) --------------------
__device__ float g_QKVc[(size_t)3 * B * SC * HS];   // Qc | Kc | Vc
__device__ float g_QKVe[(size_t)3 * B * SE * HS];   // Qe | Ke | Ve
__device__ float g_Ac[(size_t)B * SC * HS];
__device__ float g_Ae[(size_t)B * SE * HS];
// fp16 preconverted GEMM operands
__device__ __align__(256) __half g_xch[(size_t)B * SC * HS];
__device__ __align__(256) __half g_xeh[(size_t)B * SE * HS];
__device__ __align__(256) __half g_Wch[(size_t)3 * HS * HS];   // W_cq|W_ck|W_cv
__device__ __align__(256) __half g_Weh[(size_t)3 * HS * HS];   // W_eq|W_ek|W_ev
// fp16 K / V-transposed per head (attention operands)
__device__ __align__(256) __half g_Ke16[(size_t)B * NH * SE * DH];
__device__ __align__(256) __half g_Vte16[(size_t)B * NH * SE * DH];
__device__ __align__(256) __half g_Kc16[(size_t)B * NH * SC * DH];
__device__ __align__(256) __half g_Vtc16[(size_t)B * NH * SC * DH];

// ==================== helpers ====================
__device__ __forceinline__ void mma_f16(float* d, const uint32_t* a, const uint32_t* b) {
    asm volatile(
        "mma.sync.aligned.m16n8k16.row.col.f32.f16.f16.f32 "
        "{%0,%1,%2,%3}, {%4,%5,%6,%7}, {%8,%9}, {%0,%1,%2,%3};"
        : "+f"(d[0]), "+f"(d[1]), "+f"(d[2]), "+f"(d[3])
        : "r"(a[0]), "r"(a[1]), "r"(a[2]), "r"(a[3]), "r"(b[0]), "r"(b[1]));
}

__device__ __forceinline__ uint32_t packh2(float a, float b) {
    __half2 h = __floats2half2_rn(a, b);
    return *(uint32_t*)&h;
}

__device__ __forceinline__ uint32_t smem_u32(const void* p) {
    uint32_t a;
    asm("{ .reg .u64 t; cvta.to.shared.u64 t, %1; cvt.u32.u64 %0, t; }" : "=r"(a) : "l"(p));
    return a;
}

__device__ __forceinline__ void cp16(uint32_t dst, const void* src) {
    asm volatile("cp.async.cg.shared.global [%0], [%1], 16;" :: "r"(dst), "l"(src));
}

// hardware exp2 (MUFU.EX2): 1 issue slot per 32 lanes, rel err ~2^-22
__device__ __forceinline__ float ex2(float x) {
    float r;
    asm("ex2.approx.f32 %0, %1;" : "=f"(r) : "f"(x));
    return r;
}

#define CSC 0.1803368801111694f   // log2(e)/8
#define MASKADD (-24000.0f)

// ==================== merged convert: 6 weights + 2 activations ====================
__global__ __launch_bounds__(256) void cvt_all(
    const float* __restrict__ Wcq, const float* __restrict__ Wck,
    const float* __restrict__ Wcv, const float* __restrict__ Weq,
    const float* __restrict__ Wek, const float* __restrict__ Wev,
    const float* __restrict__ xc, const float* __restrict__ xe,
    __half* __restrict__ dWc, __half* __restrict__ dWe,
    __half* __restrict__ dxc, __half* __restrict__ dxe)
{
    int bid = blockIdx.x;
    const float* s;
    __half* d;
    int i;
    if (bid < 6144) {
        int z = bid >> 10;
        const float* Ws[6] = {Wcq, Wck, Wcv, Weq, Wek, Wev};
        s = Ws[z];
        d = (z < 3) ? (dWc + ((size_t)z << 20)) : (dWe + ((size_t)(z - 3) << 20));
        i = (bid & 1023) * 256 + threadIdx.x;
    } else if (bid < 8192) {
        s = xc; d = dxc;
        i = (bid - 6144) * 256 + threadIdx.x;
    } else {
        s = xe; d = dxe;
        i = (bid - 8192) * 256 + threadIdx.x;
    }
    float4 v = ((const float4*)s)[i];
    ((uint2*)d)[i] = make_uint2(packh2(v.x, v.y), packh2(v.z, v.w));
}

// ==================== GEMM: all 6 projections, 1-term fp16 ====================
#define G_RS    80
#define G_TILE  (128 * G_RS)          // 10240
#define G_AH    0
#define G_BH    (1 * G_TILE)
#define G_STAGE (2 * G_TILE)          // 20480
#define G_SMEM  (3 * G_STAGE)         // 61440

__global__ __launch_bounds__(128, 2) void gemm_f16(
    const __half* __restrict__ xeh, const __half* __restrict__ Weh,
    const __half* __restrict__ xch, const __half* __restrict__ Wch,
    const float* __restrict__ beq, const float* __restrict__ bek,
    const float* __restrict__ bev,
    const float* __restrict__ bcq, const float* __restrict__ bck,
    const float* __restrict__ bcv,
    float* __restrict__ Ce, float* __restrict__ Cc)
{
    const int z = blockIdx.z;
    const __half *Ah, *Wz;
    float* C;
    const float* bias;
    if (z < 3) {
        Ah = xeh;
        Wz = Weh + ((size_t)z << 20);
        C = Ce + (size_t)z * (B * SE) * HS;
        bias = (z == 0) ? beq : ((z == 1) ? bek : bev);
    } else {
        if (blockIdx.y >= (B * SC) / 128) return;
        int zz = z - 3;
        Ah = xch;
        Wz = Wch + ((size_t)zz << 20);
        C = Cc + (size_t)zz * (B * SC) * HS;
        bias = (zz == 0) ? bcq : ((zz == 1) ? bck : bcv);
    }

    extern __shared__ char smem[];
    const uint32_t sb = smem_u32(smem);
    const int tid = threadIdx.x;
    const int wid = tid >> 5;
    const int lane = tid & 31;
    const int g = lane >> 2;
    const int t = lane & 3;
    const int wm = wid >> 1;
    const int wn = wid & 1;
    const int bm = blockIdx.y * 128;
    const int bn = blockIdx.x * 128;

    const char* csrc[8];
    uint32_t cdst[8];
#pragma unroll
    for (int q = 0; q < 8; q++) {
        int f = q * 128 + tid;
        int tile = f >> 9;
        int idx = f & 511;
        int r = idx >> 2, col = idx & 3;
        cdst[q] = (uint32_t)(tile * G_TILE + r * G_RS + col * 16);
        if (tile == 0) csrc[q] = (const char*)(Ah + (size_t)(bm + r) * HS + col * 8);
        else           csrc[q] = (const char*)(Wz + (size_t)(bn + r) * HS + col * 8);
    }

    const int NC = HS / 32;

#pragma unroll
    for (int st = 0; st < 3; st++) {
        uint32_t db = sb + st * G_STAGE;
#pragma unroll
        for (int q = 0; q < 8; q++)
            cp16(db + cdst[q], csrc[q] + st * 64);
        asm volatile("cp.async.commit_group;");
    }

    float acc[4][8][4];
#pragma unroll
    for (int i = 0; i < 4; i++)
#pragma unroll
        for (int j = 0; j < 8; j++)
#pragma unroll
            for (int k = 0; k < 4; k++) acc[i][j][k] = 0.f;

    for (int c = 0; c < NC; c++) {
        asm volatile("cp.async.wait_group 2;");
        __syncthreads();

        const char* buf = smem + (c % 3) * G_STAGE;
#pragma unroll
        for (int s = 0; s < 2; s++) {
            const int kb = s * 32 + 4 * t;
            uint32_t ah[4][4];
#pragma unroll
            for (int i = 0; i < 4; i++) {
                int r = wm * 64 + 16 * i + g;
                const char* pa = buf + G_AH + r * G_RS + kb;
                ah[i][0] = *(const uint32_t*)(pa);
                ah[i][1] = *(const uint32_t*)(pa + 8 * G_RS);
                ah[i][2] = *(const uint32_t*)(pa + 16);
                ah[i][3] = *(const uint32_t*)(pa + 8 * G_RS + 16);
            }
#pragma unroll
            for (int j = 0; j < 8; j++) {
                int nr = wn * 64 + 8 * j + g;
                const char* pb = buf + G_BH + nr * G_RS + kb;
                uint32_t bh[2];
                bh[0] = *(const uint32_t*)(pb);
                bh[1] = *(const uint32_t*)(pb + 16);
#pragma unroll
                for (int i = 0; i < 4; i++)
                    mma_f16(acc[i][j], ah[i], bh);
            }
        }
        __syncthreads();

        if (c + 3 < NC) {
            uint32_t db = sb + ((c + 3) % 3) * G_STAGE;
            int koff = (c + 3) * 64;
#pragma unroll
            for (int q = 0; q < 8; q++)
                cp16(db + cdst[q], csrc[q] + koff);
        }
        asm volatile("cp.async.commit_group;");
    }

#pragma unroll
    for (int i = 0; i < 4; i++) {
        int row0 = bm + wm * 64 + 16 * i + g;
#pragma unroll
        for (int j = 0; j < 8; j++) {
            int col = bn + wn * 64 + 8 * j + 2 * t;
            float2 bv2 = *(const float2*)(bias + col);
            *(float2*)(C + (size_t)row0 * HS + col) =
                make_float2(acc[i][j][0] + bv2.x, acc[i][j][1] + bv2.y);
            *(float2*)(C + (size_t)(row0 + 8) * HS + col) =
                make_float2(acc[i][j][2] + bv2.x, acc[i][j][3] + bv2.y);
        }
    }
}

// ==================== K/V prep (merged): fp32 -> fp16, V transposed ==============
__global__ __launch_bounds__(256) void prep_all(
    const float* __restrict__ Kc, const float* __restrict__ Vc,
    __half* __restrict__ Kc16, __half* __restrict__ Vtc16,
    const float* __restrict__ Ke, const float* __restrict__ Ve,
    __half* __restrict__ Ke16, __half* __restrict__ Vte16)
{
    __shared__ float vs[64][65];
    const int tid = threadIdx.x;
    const int b = blockIdx.z, h = blockIdx.y;
    const int bh = b * NH + h;

    const float *K, *V;
    __half *Kh, *Vth;
    int Sk, s0;
    if (blockIdx.x < SC / 64) {
        K = Kc; V = Vc; Kh = Kc16; Vth = Vtc16; Sk = SC;
        s0 = blockIdx.x * 64;
    } else {
        K = Ke; V = Ve; Kh = Ke16; Vth = Vte16; Sk = SE;
        s0 = (blockIdx.x - SC / 64) * 64;
    }

#pragma unroll
    for (int i = 0; i < 4; i++) {
        int f = tid + 256 * i;
        int r = f >> 4, c4 = f & 15;
        float4 v = *(const float4*)(K + (size_t)(b * Sk + s0 + r) * HS + h * DH + c4 * 4);
        size_t o = ((size_t)(bh * Sk + s0 + r)) * DH + c4 * 4;
        *(uint2*)(Kh + o) = make_uint2(packh2(v.x, v.y), packh2(v.z, v.w));
    }
#pragma unroll
    for (int i = 0; i < 4; i++) {
        int f = tid + 256 * i;
        int r = f >> 4, c4 = f & 15;
        float4 v = *(const float4*)(V + (size_t)(b * Sk + s0 + r) * HS + h * DH + c4 * 4);
        vs[r][c4 * 4 + 0] = v.x;
        vs[r][c4 * 4 + 1] = v.y;
        vs[r][c4 * 4 + 2] = v.z;
        vs[r][c4 * 4 + 3] = v.w;
    }
    __syncthreads();
#pragma unroll
    for (int i = 0; i < 8; i++) {
        int f = tid + 256 * i;
        int d = f >> 5, sp = f & 31;
        float v0 = vs[2 * sp][d], v1 = vs[2 * sp + 1][d];
        size_t o = ((size_t)(bh * DH + d)) * Sk + s0 + 2 * sp;
        *(uint32_t*)(Vth + o) = packh2(v0, v1);
    }
}

// ==================== attention: 1-term fp16, MUFU exp, 2 CTAs/SM ================
#define AK    0
#define AV    9216
#define AMS   18432
#define ABUF  18688
#define ASMEM (2 * ABUF)   // 37376

__global__ __launch_bounds__(256, 2) void attn_all(
    const float* __restrict__ Qc, const __half* __restrict__ Ke,
    const __half* __restrict__ Vte, const int* __restrict__ me,
    float* __restrict__ Ac,
    const float* __restrict__ Qe, const __half* __restrict__ Kc,
    const __half* __restrict__ Vtc, const int* __restrict__ mc,
    float* __restrict__ Ae)
{
    extern __shared__ char sm[];
    const uint32_t sb = smem_u32(sm);
    const int tid = threadIdx.x;
    const int wid = tid >> 5;
    const int lane = tid & 31;
    const int g = lane >> 2;
    const int t = lane & 3;
    const int b = blockIdx.z, h = blockIdx.y;
    const int bx = blockIdx.x;
    const int bh = b * NH + h;

    const float* Q;
    const __half* K;
    const __half* Vt;
    const int* mask;
    float* O;
    int Sq, Sk, q0;
    if (bx < SC / 128) {
        Q = Qc; K = Ke; Vt = Vte; mask = me; O = Ac;
        Sq = SC; Sk = SE; q0 = bx * 128;
    } else {
        Q = Qe; K = Kc; Vt = Vtc; mask = mc; O = Ae;
        Sq = SE; Sk = SC; q0 = (bx - SC / 128) * 128;
    }
    const int nt = Sk / 64;

    const char* csrc[4];
    uint32_t cdst[4];
#pragma unroll
    for (int q = 0; q < 4; q++) {
        int sub = ((q & 1) << 8) | tid;
        int r = sub >> 3, c = sub & 7;
        if (q < 2) {
            csrc[q] = (const char*)(K + (size_t)(bh * (size_t)Sk + r) * DH + c * 8);
            cdst[q] = AK + (uint32_t)(r * 144 + c * 16);
        } else {
            csrc[q] = (const char*)(Vt + (size_t)(bh * DH + r) * (size_t)Sk + c * 8);
            cdst[q] = AV + (uint32_t)(r * 144 + c * 16);
        }
    }
    const char* msrc = (const char*)(mask + (size_t)b * Sk) + tid * 16;

    {
#pragma unroll
        for (int q = 0; q < 4; q++)
            cp16(sb + cdst[q], csrc[q]);
        if (tid < 16) cp16(sb + AMS + tid * 16, msrc);
        asm volatile("cp.async.commit_group;");
    }
    if (nt > 1) {
#pragma unroll
        for (int q = 0; q < 4; q++)
            cp16(sb + ABUF + cdst[q], csrc[q] + ((q < 2) ? 8192 : 128));
        if (tid < 16) cp16(sb + ABUF + AMS + tid * 16, msrc + 256);
    }
    asm volatile("cp.async.commit_group;");

    // Q fragments from gmem, pre-scaled by CSC
    uint32_t qh[4][4];
    {
        const float* qp0 = Q + (size_t)(b * Sq + q0 + wid * 16 + g) * HS + h * DH;
        const float* qp8 = qp0 + 8 * HS;
#pragma unroll
        for (int kk = 0; kk < 4; kk++) {
            int c0 = 16 * kk + 2 * t;
            float2 x0 = *(const float2*)(qp0 + c0);
            float2 x1 = *(const float2*)(qp8 + c0);
            float2 x2 = *(const float2*)(qp0 + c0 + 8);
            float2 x3 = *(const float2*)(qp8 + c0 + 8);
            qh[kk][0] = packh2(x0.x * CSC, x0.y * CSC);
            qh[kk][1] = packh2(x1.x * CSC, x1.y * CSC);
            qh[kk][2] = packh2(x2.x * CSC, x2.y * CSC);
            qh[kk][3] = packh2(x3.x * CSC, x3.y * CSC);
        }
    }

    float oacc[8][4];
#pragma unroll
    for (int j = 0; j < 8; j++)
#pragma unroll
        for (int k = 0; k < 4; k++) oacc[j][k] = 0.f;
    float l0 = 0.f, l1 = 0.f;

    for (int it = 0; it < nt; it++) {
        if (it + 1 < nt) { asm volatile("cp.async.wait_group 1;"); }
        else             { asm volatile("cp.async.wait_group 0;"); }
        __syncthreads();

        char* buf = sm + (it & 1) * ABUF;
        const int* ms = (const int*)(buf + AMS);

        float sacc[8][4];
#pragma unroll
        for (int j = 0; j < 8; j++)
#pragma unroll
            for (int k = 0; k < 4; k++) sacc[j][k] = 0.f;

#pragma unroll
        for (int kk = 0; kk < 4; kk++) {
#pragma unroll
            for (int j = 0; j < 8; j++) {
                int off = (8 * j + g) * 144 + (16 * kk + 2 * t) * 2;
                uint32_t kh2[2];
                kh2[0] = *(const uint32_t*)(buf + AK + off);
                kh2[1] = *(const uint32_t*)(buf + AK + off + 16);
                mma_f16(sacc[j], qh[kk], kh2);
            }
        }

        // ---- max-free softmax with MUFU exp2 ----
#pragma unroll
        for (int j = 0; j < 8; j++) {
            int2 mv = *(const int2*)(ms + 8 * j + 2 * t);
            float a0 = mv.x ? 0.f : MASKADD;
            float a1 = mv.y ? 0.f : MASKADD;
            sacc[j][0] = ex2(sacc[j][0] + a0);
            sacc[j][1] = ex2(sacc[j][1] + a1);
            sacc[j][2] = ex2(sacc[j][2] + a0);
            sacc[j][3] = ex2(sacc[j][3] + a1);
            l0 += sacc[j][0] + sacc[j][1];
            l1 += sacc[j][2] + sacc[j][3];
        }

        uint32_t ph[4][4];
#pragma unroll
        for (int s = 0; s < 4; s++) {
            const float* pa = sacc[2 * s];
            const float* pb = sacc[2 * s + 1];
            ph[s][0] = packh2(pa[0], pa[1]);
            ph[s][1] = packh2(pa[2], pa[3]);
            ph[s][2] = packh2(pb[0], pb[1]);
            ph[s][3] = packh2(pb[2], pb[3]);
        }

#pragma unroll
        for (int s = 0; s < 4; s++) {
#pragma unroll
            for (int j = 0; j < 8; j++) {
                int off = (8 * j + g) * 144 + (16 * s + 2 * t) * 2;
                uint32_t vh2[2];
                vh2[0] = *(const uint32_t*)(buf + AV + off);
                vh2[1] = *(const uint32_t*)(buf + AV + off + 16);
                mma_f16(oacc[j], ph[s], vh2);
            }
        }

        __syncthreads();
        if (it + 2 < nt) {
            size_t kaK = (size_t)(it + 2) * 8192;
            size_t kaV = (size_t)(it + 2) * 128;
            uint32_t db = sb + (it & 1) * ABUF;
#pragma unroll
            for (int q = 0; q < 4; q++)
                cp16(db + cdst[q], csrc[q] + ((q < 2) ? kaK : kaV));
            if (tid < 16) cp16(db + AMS + tid * 16, msrc + (size_t)(it + 2) * 256);
        }
        asm volatile("cp.async.commit_group;");
    }

    l0 += __shfl_xor_sync(0xffffffffu, l0, 1);
    l0 += __shfl_xor_sync(0xffffffffu, l0, 2);
    l1 += __shfl_xor_sync(0xffffffffu, l1, 1);
    l1 += __shfl_xor_sync(0xffffffffu, l1, 2);
    float inv0 = 1.f / l0;
    float inv1 = 1.f / l1;
    int row0 = q0 + wid * 16 + g;
#pragma unroll
    for (int j = 0; j < 8; j++) {
        int col = h * DH + 8 * j + 2 * t;
        *(float2*)(O + (size_t)(b * Sq + row0) * HS + col) =
            make_float2(oacc[j][0] * inv0, oacc[j][1] * inv0);
        *(float2*)(O + (size_t)(b * Sq + row0 + 8) * HS + col) =
            make_float2(oacc[j][2] * inv1, oacc[j][3] * inv1);
    }
}

// ==================== fused residual add + LayerNorm (merged) ====================
__global__ __launch_bounds__(256) void add_ln_all(
    const float* __restrict__ xc, const float* __restrict__ Ac,
    const float* __restrict__ xe, const float* __restrict__ Ae,
    const float* __restrict__ g, const float* __restrict__ bb,
    float* __restrict__ out)
{
    int row = blockIdx.x;
    const float *x, *att;
    if (row < B * SC) { x = xc + (size_t)row * HS; att = Ac + (size_t)row * HS; }
    else {
        int r = row - B * SC;
        x = xe + (size_t)r * HS; att = Ae + (size_t)r * HS;
    }
    int tid = threadIdx.x;
    float4 xv = ((const float4*)x)[tid];
    float4 av = ((const float4*)att)[tid];
    float v0 = xv.x + av.x, v1 = xv.y + av.y, v2 = xv.z + av.z, v3 = xv.w + av.w;

    float s = v0 + v1 + v2 + v3;
    float sq = v0 * v0 + v1 * v1 + v2 * v2 + v3 * v3;
#pragma unroll
    for (int off = 16; off > 0; off >>= 1) {
        s  += __shfl_xor_sync(0xffffffffu, s, off);
        sq += __shfl_xor_sync(0xffffffffu, sq, off);
    }
    __shared__ float ss[8], ssq[8];
    int wid = tid >> 5, lane = tid & 31;
    if (lane == 0) { ss[wid] = s; ssq[wid] = sq; }
    __syncthreads();
    s = 0.f; sq = 0.f;
#pragma unroll
    for (int w = 0; w < 8; w++) { s += ss[w]; sq += ssq[w]; }

    float mu = s * (1.f / HS);
    float var = sq * (1.f / HS) - mu * mu;
    float r = rsqrtf(var + 1e-5f);

    float4 gv = ((const float4*)g)[tid];
    float4 bv = ((const float4*)bb)[tid];
    float4 ov = make_float4((v0 - mu) * r * gv.x + bv.x,
                            (v1 - mu) * r * gv.y + bv.y,
                            (v2 - mu) * r * gv.z + bv.z,
                            (v3 - mu) * r * gv.w + bv.w);
    ((float4*)(out + (size_t)row * HS))[tid] = ov;
}

// ==================== launcher ====================
extern "C" void kernel_launch(void* const* d_in, const int* in_sizes, int n_in,
                              void* d_out, int out_size)
{
    (void)in_sizes; (void)n_in; (void)out_size;
    const float* x_c   = (const float*)d_in[0];
    const float* x_e   = (const float*)d_in[1];
    const int*   msk_c = (const int*)d_in[2];
    const int*   msk_e = (const int*)d_in[3];
    const float* W_cq = (const float*)d_in[4];  const float* b_cq = (const float*)d_in[5];
    const float* W_ek = (const float*)d_in[6];  const float* b_ek = (const float*)d_in[7];
    const float* W_ev = (const float*)d_in[8];  const float* b_ev = (const float*)d_in[9];
    const float* W_eq = (const float*)d_in[10]; const float* b_eq = (const float*)d_in[11];
    const float* W_ck = (const float*)d_in[12]; const float* b_ck = (const float*)d_in[13];
    const float* W_cv = (const float*)d_in[14]; const float* b_cv = (const float*)d_in[15];
    const float* ln_g = (const float*)d_in[16]; const float* ln_b = (const float*)d_in[17];
    float* out = (float*)d_out;

    float *QKVc, *QKVe, *Ac, *Ae;
    cudaGetSymbolAddress((void**)&QKVc, g_QKVc);
    cudaGetSymbolAddress((void**)&QKVe, g_QKVe);
    cudaGetSymbolAddress((void**)&Ac, g_Ac);
    cudaGetSymbolAddress((void**)&Ae, g_Ae);
    __half *xch, *xeh, *Wch, *Weh;
    cudaGetSymbolAddress((void**)&xch, g_xch);
    cudaGetSymbolAddress((void**)&xeh, g_xeh);
    cudaGetSymbolAddress((void**)&Wch, g_Wch);
    cudaGetSymbolAddress((void**)&Weh, g_Weh);
    __half *Ke16, *Vte16, *Kc16, *Vtc16;
    cudaGetSymbolAddress((void**)&Ke16, g_Ke16);
    cudaGetSymbolAddress((void**)&Vte16, g_Vte16);
    cudaGetSymbolAddress((void**)&Kc16, g_Kc16);
    cudaGetSymbolAddress((void**)&Vtc16, g_Vtc16);

    cudaFuncSetAttribute(gemm_f16, cudaFuncAttributeMaxDynamicSharedMemorySize, G_SMEM);
    cudaFuncSetAttribute(attn_all, cudaFuncAttributeMaxDynamicSharedMemorySize, ASMEM);

    const int Mc = B * SC;   // 2048
    const int Me = B * SE;   // 8192

    cvt_all<<<16384, 256>>>(W_cq, W_ck, W_cv, W_eq, W_ek, W_ev, x_c, x_e,
                            Wch, Weh, xch, xeh);

    gemm_f16<<<dim3(8, Me / 128, 6), 128, G_SMEM>>>(
        xeh, Weh, xch, Wch,
        b_eq, b_ek, b_ev, b_cq, b_ck, b_cv,
        QKVe, QKVc);

    float* Qc = QKVc;
    float* Kc = QKVc + (size_t)Mc * HS;
    float* Vc = QKVc + (size_t)2 * Mc * HS;
    float* Qe = QKVe;
    float* Ke = QKVe + (size_t)Me * HS;
    float* Ve = QKVe + (size_t)2 * Me * HS;

    prep_all<<<dim3(SC / 64 + SE / 64, NH, B), 256>>>(
        Kc, Vc, Kc16, Vtc16, Ke, Ve, Ke16, Vte16);

    attn_all<<<dim3(SC / 128 + SE / 128, NH, B), 256, ASMEM>>>(
        Qc, Ke16, Vte16, msk_e, Ac,
        Qe, Kc16, Vtc16, msk_c, Ae);

    add_ln_all<<<Mc + Me, 256>>>(x_c, Ac, x_e, Ae, ln_g, ln_b, out);
}